// round 1
// baseline (speedup 1.0000x reference)
#include <cuda_runtime.h>
#include <math.h>

// ---------------- problem constants ----------------
#define BATCH   2
#define S_LEN   2048
#define NROWS   (BATCH * S_LEN)     // 4096
#define DIM_    1024
#define NH      8
#define Q_C_    128
#define Q_NOPE_ 96
#define Q_ROPE_ 32
#define KV_C_   128
#define K_NOPE_ 64
#define K_ROPE_ 64
#define V_HD_   256
#define QDIM    128                  // Q_NOPE + Q_ROPE
#define KDIM    128                  // K_NOPE + K_ROPE

// ---------------- scratch (static device arrays; no allocations) ----------------
__device__ float g_cq   [(size_t)NROWS * Q_C_];           // 2 MB
__device__ float g_ckvkr[(size_t)NROWS * 192];            // 3 MB
__device__ float g_q    [(size_t)NROWS * 1024];           // 16 MB
__device__ float g_kv   [(size_t)NROWS * 2560];           // 40 MB
__device__ float g_qs   [(size_t)BATCH * NH * S_LEN * QDIM];   // 16 MB
__device__ float g_ks   [(size_t)BATCH * NH * S_LEN * KDIM];   // 16 MB
__device__ float g_vs   [(size_t)BATCH * NH * S_LEN * V_HD_];  // 32 MB
__device__ float g_attn [(size_t)NROWS * (NH * V_HD_)];        // 32 MB

// ---------------- generic tiled GEMM: C = A(lda) @ B + bias ----------------
// BM=128, BN=64, BK=16, 256 threads, 8x4 micro-tile.
// Requires: M % 128 == 0, N % 4 == 0, K % 16 == 0 (true for all call sites).
#define BM 128
#define BN 64
#define BKK 16

__global__ __launch_bounds__(256)
void gemm_bias_kernel(const float* __restrict__ A, int lda,
                      const float* __restrict__ B,
                      const float* __restrict__ bias,
                      float* __restrict__ C,
                      int M, int N, int K)
{
    __shared__ float As[BKK][BM + 4];
    __shared__ float Bs[BKK][BN + 4];

    int tid = threadIdx.x;
    int tx = tid & 15;          // 0..15 -> 4 cols each
    int ty = tid >> 4;          // 0..15 -> 8 rows each
    int m0 = blockIdx.y * BM;
    int n0 = blockIdx.x * BN;

    float acc[8][4];
#pragma unroll
    for (int i = 0; i < 8; i++)
#pragma unroll
        for (int j = 0; j < 4; j++) acc[i][j] = 0.f;

    int ar = tid >> 2;          // 0..63
    int ac = (tid & 3) * 4;     // 0,4,8,12
    int br = tid >> 4;          // 0..15
    int bc = (tid & 15) * 4;    // 0..60

    for (int k0 = 0; k0 < K; k0 += BKK) {
        // load A tile (transposed into As[k][m])
#pragma unroll
        for (int p = 0; p < 2; p++) {
            int i = ar + p * 64;
            float4 v = *(const float4*)(A + (size_t)(m0 + i) * lda + k0 + ac);
            As[ac + 0][i] = v.x;
            As[ac + 1][i] = v.y;
            As[ac + 2][i] = v.z;
            As[ac + 3][i] = v.w;
        }
        // load B tile
        {
            float4 v;
            if (n0 + bc + 3 < N) {
                v = *(const float4*)(B + (size_t)(k0 + br) * N + n0 + bc);
            } else {
                v.x = (n0 + bc + 0 < N) ? B[(size_t)(k0 + br) * N + n0 + bc + 0] : 0.f;
                v.y = (n0 + bc + 1 < N) ? B[(size_t)(k0 + br) * N + n0 + bc + 1] : 0.f;
                v.z = (n0 + bc + 2 < N) ? B[(size_t)(k0 + br) * N + n0 + bc + 2] : 0.f;
                v.w = (n0 + bc + 3 < N) ? B[(size_t)(k0 + br) * N + n0 + bc + 3] : 0.f;
            }
            *(float4*)&Bs[br][bc] = v;
        }
        __syncthreads();
#pragma unroll
        for (int k = 0; k < BKK; k++) {
            float4 a0 = *(float4*)&As[k][ty * 8];
            float4 a1 = *(float4*)&As[k][ty * 8 + 4];
            float4 b4 = *(float4*)&Bs[k][tx * 4];
            float av[8] = {a0.x, a0.y, a0.z, a0.w, a1.x, a1.y, a1.z, a1.w};
            float bv[4] = {b4.x, b4.y, b4.z, b4.w};
#pragma unroll
            for (int i = 0; i < 8; i++)
#pragma unroll
                for (int j = 0; j < 4; j++)
                    acc[i][j] += av[i] * bv[j];
        }
        __syncthreads();
    }

    int nc = n0 + tx * 4;
    if (nc + 3 < N) {
        float4 bv = *(const float4*)(bias + nc);
#pragma unroll
        for (int i = 0; i < 8; i++) {
            int m = m0 + ty * 8 + i;
            float4 o;
            o.x = acc[i][0] + bv.x;
            o.y = acc[i][1] + bv.y;
            o.z = acc[i][2] + bv.z;
            o.w = acc[i][3] + bv.w;
            *(float4*)(C + (size_t)m * N + nc) = o;
        }
    } else {
#pragma unroll
        for (int i = 0; i < 8; i++) {
            int m = m0 + ty * 8 + i;
#pragma unroll
            for (int j = 0; j < 4; j++)
                if (nc + j < N)
                    C[(size_t)m * N + nc + j] = acc[i][j] + bias[nc + j];
        }
    }
}

// ---------------- RMSNorm over first 128 cols of each row ----------------
__global__ void rmsnorm_kernel(float* __restrict__ data, const float* __restrict__ w,
                               int rows, int stride)
{
    int row = blockIdx.x * 8 + (threadIdx.x >> 5);
    int lane = threadIdx.x & 31;
    if (row >= rows) return;
    float* p = data + (size_t)row * stride;
    float4 v = *(float4*)(p + lane * 4);
    float ss = v.x * v.x + v.y * v.y + v.z * v.z + v.w * v.w;
#pragma unroll
    for (int o = 16; o; o >>= 1) ss += __shfl_xor_sync(0xffffffffu, ss, o);
    float sc = rsqrtf(ss * (1.f / 128.f) + 1e-8f);
    float4 wv = *(const float4*)(w + lane * 4);
    v.x *= wv.x * sc;
    v.y *= wv.y * sc;
    v.z *= wv.z * sc;
    v.w *= wv.w * sc;
    *(float4*)(p + lane * 4) = v;
}

// ---------------- pack Q with RoPE:  g_qs[b,h,s,d] ----------------
__global__ void pack_q_kernel(const float* __restrict__ q, const int* __restrict__ pos,
                              float* __restrict__ qs)
{
    int idx = blockIdx.x * blockDim.x + threadIdx.x;
    if (idx >= BATCH * NH * S_LEN * QDIM) return;
    int d = idx & 127;
    int s = (idx >> 7) & (S_LEN - 1);
    int h = (idx >> 18) & 7;
    int b = idx >> 21;
    int r = b * S_LEN + s;
    float val;
    if (d < Q_NOPE_) {
        val = q[(size_t)r * 1024 + h * Q_NOPE_ + d];
    } else {
        int j = d - Q_NOPE_;
        int jp = j & ~1;
        int i = jp >> 1;
        const float* base = q + (size_t)r * 1024 + NH * Q_NOPE_ + h * Q_ROPE_;
        float xe = base[jp];
        float xo = base[jp + 1];
        float p = (float)pos[r];
        float inv = powf(10000.f, -(float)(2 * i) / (float)Q_ROPE_);
        float ang = p * inv;
        float sn, cs;
        sincosf(ang, &sn, &cs);
        val = (j & 1) ? (xe * sn + xo * cs) : (xe * cs - xo * sn);
    }
    qs[idx] = val;
}

// ---------------- pack K with RoPE:  g_ks[b,h,s,d] ----------------
__global__ void pack_k_kernel(const float* __restrict__ kv, const float* __restrict__ ckvkr,
                              const int* __restrict__ pos, float* __restrict__ ks)
{
    int idx = blockIdx.x * blockDim.x + threadIdx.x;
    if (idx >= BATCH * NH * S_LEN * KDIM) return;
    int d = idx & 127;
    int s = (idx >> 7) & (S_LEN - 1);
    int h = (idx >> 18) & 7;
    int b = idx >> 21;
    int r = b * S_LEN + s;
    float val;
    if (d < K_NOPE_) {
        val = kv[(size_t)r * 2560 + h * K_NOPE_ + d];
    } else {
        int j = d - K_NOPE_;
        int jp = j & ~1;
        int i = jp >> 1;
        const float* base = ckvkr + (size_t)r * 192 + KV_C_;
        float xe = base[jp];
        float xo = base[jp + 1];
        float p = (float)pos[r];
        float inv = powf(10000.f, -(float)(2 * i) / (float)K_ROPE_);
        float ang = p * inv;
        float sn, cs;
        sincosf(ang, &sn, &cs);
        val = (j & 1) ? (xe * sn + xo * cs) : (xe * cs - xo * sn);
    }
    ks[idx] = val;
}

// ---------------- pack V:  g_vs[b,h,s,d] ----------------
__global__ void pack_v_kernel(const float* __restrict__ kv, float* __restrict__ vs)
{
    int idx = blockIdx.x * blockDim.x + threadIdx.x;
    if (idx >= BATCH * NH * S_LEN * V_HD_) return;
    int d = idx & 255;
    int s = (idx >> 8) & (S_LEN - 1);
    int h = (idx >> 19) & 7;
    int b = idx >> 22;
    int r = b * S_LEN + s;
    vs[idx] = kv[(size_t)r * 2560 + NH * K_NOPE_ + h * V_HD_ + d];
}

// ---------------- flash attention ----------------
// grid (32 q-tiles, 8 heads, 2 batch), 256 threads (8 warps).
// BLOCK_M=64 (8 rows/warp), BLOCK_N=32 (lane = k-col), D=128, DV=256.
#define FLASH_SMEM_FLOATS (64 * 128 + 128 * 33 + 32 * 256)
#define FLASH_SMEM_BYTES  (FLASH_SMEM_FLOATS * 4)

__global__ __launch_bounds__(256)
void flash_kernel(const float* __restrict__ qs, const float* __restrict__ ks,
                  const float* __restrict__ vs, float* __restrict__ attn)
{
    extern __shared__ float smem[];
    float* Qs = smem;                  // [64][128]
    float* Kt = smem + 64 * 128;       // [128][33]  (d-major, stride 33)
    float* Vs = Kt + 128 * 33;         // [32][256]

    int b = blockIdx.z, h = blockIdx.y, qt = blockIdx.x;
    int tid = threadIdx.x;
    int w = tid >> 5;
    int lane = tid & 31;

    size_t bh = (size_t)(b * NH + h) * S_LEN;
    const float* Q = qs + (bh + qt * 64) * 128;
    for (int i = tid; i < 64 * 128 / 4; i += 256)
        ((float4*)Qs)[i] = ((const float4*)Q)[i];

    float m[8], l[8], o[8][8];
#pragma unroll
    for (int r = 0; r < 8; r++) {
        m[r] = -1e30f;
        l[r] = 0.f;
#pragma unroll
        for (int j = 0; j < 8; j++) o[r][j] = 0.f;
    }

    const float scale = 0.08838834764831845f;  // 1/sqrt(128)

    for (int kt = 0; kt < S_LEN / 32; kt++) {
        __syncthreads();
        // load K tile transposed: Kt[d][kcol]
        const float* K = ks + (bh + kt * 32) * 128;
        for (int kr = w; kr < 32; kr += 8) {
            float4 v4 = ((const float4*)(K + kr * 128))[lane];
            Kt[(lane * 4 + 0) * 33 + kr] = v4.x;
            Kt[(lane * 4 + 1) * 33 + kr] = v4.y;
            Kt[(lane * 4 + 2) * 33 + kr] = v4.z;
            Kt[(lane * 4 + 3) * 33 + kr] = v4.w;
        }
        // load V tile row-major
        const float* V = vs + (bh + kt * 32) * 256;
        for (int i = tid; i < 32 * 256 / 4; i += 256)
            ((float4*)Vs)[i] = ((const float4*)V)[i];
        __syncthreads();

        // scores: s[r] = Q[row] . K[lane]
        float s[8];
#pragma unroll
        for (int r = 0; r < 8; r++) s[r] = 0.f;
#pragma unroll 8
        for (int d4 = 0; d4 < 32; d4++) {
            float k0 = Kt[(4 * d4 + 0) * 33 + lane];
            float k1 = Kt[(4 * d4 + 1) * 33 + lane];
            float k2 = Kt[(4 * d4 + 2) * 33 + lane];
            float k3 = Kt[(4 * d4 + 3) * 33 + lane];
#pragma unroll
            for (int r = 0; r < 8; r++) {
                float4 q4 = *(float4*)&Qs[(w * 8 + r) * 128 + 4 * d4];
                s[r] += q4.x * k0 + q4.y * k1 + q4.z * k2 + q4.w * k3;
            }
        }

        // online softmax (per row, reduce across 32 lanes)
#pragma unroll
        for (int r = 0; r < 8; r++) {
            float sv = s[r] * scale;
            float mx = sv;
#pragma unroll
            for (int off = 16; off; off >>= 1)
                mx = fmaxf(mx, __shfl_xor_sync(0xffffffffu, mx, off));
            float mn = fmaxf(m[r], mx);
            float corr = __expf(m[r] - mn);
            float p = __expf(sv - mn);
            float ps = p;
#pragma unroll
            for (int off = 16; off; off >>= 1)
                ps += __shfl_xor_sync(0xffffffffu, ps, off);
            l[r] = l[r] * corr + ps;
            m[r] = mn;
#pragma unroll
            for (int j = 0; j < 8; j++) o[r][j] *= corr;
            s[r] = p;  // keep un-normalized prob for this lane's k-col
        }

        // O += P @ V
#pragma unroll 4
        for (int k = 0; k < 32; k++) {
            float v0 = Vs[k * 256 + lane + 0];
            float v1 = Vs[k * 256 + lane + 32];
            float v2 = Vs[k * 256 + lane + 64];
            float v3 = Vs[k * 256 + lane + 96];
            float v4 = Vs[k * 256 + lane + 128];
            float v5 = Vs[k * 256 + lane + 160];
            float v6 = Vs[k * 256 + lane + 192];
            float v7 = Vs[k * 256 + lane + 224];
#pragma unroll
            for (int r = 0; r < 8; r++) {
                float pv = __shfl_sync(0xffffffffu, s[r], k);
                o[r][0] += pv * v0;
                o[r][1] += pv * v1;
                o[r][2] += pv * v2;
                o[r][3] += pv * v3;
                o[r][4] += pv * v4;
                o[r][5] += pv * v5;
                o[r][6] += pv * v6;
                o[r][7] += pv * v7;
            }
        }
    }

    // write out to attn[b, s, h*256 + dv]  (layout for the final GEMM)
#pragma unroll
    for (int r = 0; r < 8; r++) {
        float inv = 1.f / l[r];
        int row = b * S_LEN + qt * 64 + w * 8 + r;
        float* dst = attn + (size_t)row * (NH * V_HD_) + h * V_HD_ + lane;
#pragma unroll
        for (int j = 0; j < 8; j++) dst[32 * j] = o[r][j] * inv;
    }
}

// ---------------- host launcher ----------------
extern "C" void kernel_launch(void* const* d_in, const int* in_sizes, int n_in,
                              void* d_out, int out_size)
{
    const float* x         = (const float*)d_in[0];
    const int*   pos       = (const int*)  d_in[1];
    const float* w_dq_w    = (const float*)d_in[2];
    const float* w_dq_b    = (const float*)d_in[3];
    const float* q_norm_w  = (const float*)d_in[4];
    const float* w_uq_qr_w = (const float*)d_in[5];
    const float* w_uq_qr_b = (const float*)d_in[6];
    const float* w_dkv_kr_w= (const float*)d_in[7];
    const float* w_dkv_kr_b= (const float*)d_in[8];
    const float* kv_norm_w = (const float*)d_in[9];
    const float* w_uk_uv_w = (const float*)d_in[10];
    const float* w_uk_uv_b = (const float*)d_in[11];
    const float* w_o_w     = (const float*)d_in[12];
    const float* w_o_b     = (const float*)d_in[13];
    float* out = (float*)d_out;

    float *cq, *ckvkr, *q, *kv, *qsb, *ksb, *vsb, *attn;
    cudaGetSymbolAddress((void**)&cq,    g_cq);
    cudaGetSymbolAddress((void**)&ckvkr, g_ckvkr);
    cudaGetSymbolAddress((void**)&q,     g_q);
    cudaGetSymbolAddress((void**)&kv,    g_kv);
    cudaGetSymbolAddress((void**)&qsb,   g_qs);
    cudaGetSymbolAddress((void**)&ksb,   g_ks);
    cudaGetSymbolAddress((void**)&vsb,   g_vs);
    cudaGetSymbolAddress((void**)&attn,  g_attn);

    cudaFuncSetAttribute(flash_kernel, cudaFuncAttributeMaxDynamicSharedMemorySize,
                         FLASH_SMEM_BYTES);

    dim3 blk(256);

    // cq = rmsnorm(x @ w_dq + b)
    gemm_bias_kernel<<<dim3(128 / BN, NROWS / BM), blk>>>(x, DIM_, w_dq_w, w_dq_b, cq,
                                                          NROWS, 128, DIM_);
    rmsnorm_kernel<<<NROWS / 8, 256>>>(cq, q_norm_w, NROWS, 128);

    // ckv_kr = x @ w_dkv_kr + b ; rmsnorm first 128 cols
    gemm_bias_kernel<<<dim3(192 / BN, NROWS / BM), blk>>>(x, DIM_, w_dkv_kr_w, w_dkv_kr_b,
                                                          ckvkr, NROWS, 192, DIM_);
    rmsnorm_kernel<<<NROWS / 8, 256>>>(ckvkr, kv_norm_w, NROWS, 192);

    // q = cq @ w_uq_qr + b
    gemm_bias_kernel<<<dim3(1024 / BN, NROWS / BM), blk>>>(cq, 128, w_uq_qr_w, w_uq_qr_b,
                                                           q, NROWS, 1024, 128);

    // kv = ckv @ w_uk_uv + b   (A = first 128 cols of ckvkr, lda=192)
    gemm_bias_kernel<<<dim3(2560 / BN, NROWS / BM), blk>>>(ckvkr, 192, w_uk_uv_w, w_uk_uv_b,
                                                           kv, NROWS, 2560, 128);

    // pack q/k/v with rope
    pack_q_kernel<<<(BATCH * NH * S_LEN * QDIM) / 256, 256>>>(q, pos, qsb);
    pack_k_kernel<<<(BATCH * NH * S_LEN * KDIM) / 256, 256>>>(kv, ckvkr, pos, ksb);
    pack_v_kernel<<<(BATCH * NH * S_LEN * V_HD_) / 256, 256>>>(kv, vsb);

    // attention
    flash_kernel<<<dim3(S_LEN / 64, NH, BATCH), 256, FLASH_SMEM_BYTES>>>(qsb, ksb, vsb, attn);

    // out = attn @ w_o + b
    gemm_bias_kernel<<<dim3(1024 / BN, NROWS / BM), blk>>>(attn, NH * V_HD_, w_o_w, w_o_b,
                                                           out, NROWS, 1024, NH * V_HD_);
}

// round 2
// speedup vs baseline: 2.3791x; 2.3791x over previous
#include <cuda_runtime.h>
#include <math.h>
#include <stdint.h>

// ---------------- problem constants ----------------
#define BATCH   2
#define S_LEN   2048
#define NROWS   (BATCH * S_LEN)     // 4096
#define DIM_    1024
#define NH      8
#define Q_C_    128
#define Q_NOPE_ 96
#define Q_ROPE_ 32
#define KV_C_   128
#define K_NOPE_ 64
#define K_ROPE_ 64
#define V_HD_   256
#define QDIM    128
#define KDIM    128
#define SM_SCALE 0.08838834764831845f   // 1/sqrt(128)

// ---------------- scratch (static device arrays; no allocations) ----------------
__device__ float g_cq   [(size_t)NROWS * Q_C_];
__device__ float g_ckvkr[(size_t)NROWS * 192];
__device__ float g_q    [(size_t)NROWS * 1024];
__device__ float g_kv   [(size_t)NROWS * 2560];
__device__ float g_qs   [(size_t)BATCH * NH * S_LEN * QDIM];
__device__ float g_ks   [(size_t)BATCH * NH * S_LEN * KDIM];
__device__ float g_vs   [(size_t)BATCH * NH * S_LEN * V_HD_];
__device__ float g_attn [(size_t)NROWS * (NH * V_HD_)];

// ---------------- helpers ----------------
__device__ __forceinline__ float to_tf32(float x) {
    uint32_t u;
    asm("cvt.rna.tf32.f32 %0, %1;" : "=r"(u) : "f"(x));
    return __uint_as_float(u);
}

__device__ __forceinline__ void mma_tf32(float* c, uint32_t a0, uint32_t a1,
                                         uint32_t a2, uint32_t a3,
                                         uint32_t b0, uint32_t b1) {
    asm volatile(
        "mma.sync.aligned.m16n8k8.row.col.f32.tf32.tf32.f32 "
        "{%0,%1,%2,%3}, {%4,%5,%6,%7}, {%8,%9}, {%0,%1,%2,%3};"
        : "+f"(c[0]), "+f"(c[1]), "+f"(c[2]), "+f"(c[3])
        : "r"(a0), "r"(a1), "r"(a2), "r"(a3), "r"(b0), "r"(b1));
}

// ---------------- generic tiled GEMM: C = A(lda) @ B + bias (fp32 SIMT) ----------------
#define BM 128
#define BN 64
#define BKK 16

__global__ __launch_bounds__(256)
void gemm_bias_kernel(const float* __restrict__ A, int lda,
                      const float* __restrict__ B,
                      const float* __restrict__ bias,
                      float* __restrict__ C,
                      int M, int N, int K)
{
    __shared__ float As[BKK][BM + 4];
    __shared__ float Bs[BKK][BN + 4];

    int tid = threadIdx.x;
    int tx = tid & 15;
    int ty = tid >> 4;
    int m0 = blockIdx.y * BM;
    int n0 = blockIdx.x * BN;

    float acc[8][4];
#pragma unroll
    for (int i = 0; i < 8; i++)
#pragma unroll
        for (int j = 0; j < 4; j++) acc[i][j] = 0.f;

    int ar = tid >> 2;
    int ac = (tid & 3) * 4;
    int br = tid >> 4;
    int bc = (tid & 15) * 4;

    for (int k0 = 0; k0 < K; k0 += BKK) {
#pragma unroll
        for (int p = 0; p < 2; p++) {
            int i = ar + p * 64;
            float4 v = *(const float4*)(A + (size_t)(m0 + i) * lda + k0 + ac);
            As[ac + 0][i] = v.x;
            As[ac + 1][i] = v.y;
            As[ac + 2][i] = v.z;
            As[ac + 3][i] = v.w;
        }
        {
            float4 v;
            if (n0 + bc + 3 < N) {
                v = *(const float4*)(B + (size_t)(k0 + br) * N + n0 + bc);
            } else {
                v.x = (n0 + bc + 0 < N) ? B[(size_t)(k0 + br) * N + n0 + bc + 0] : 0.f;
                v.y = (n0 + bc + 1 < N) ? B[(size_t)(k0 + br) * N + n0 + bc + 1] : 0.f;
                v.z = (n0 + bc + 2 < N) ? B[(size_t)(k0 + br) * N + n0 + bc + 2] : 0.f;
                v.w = (n0 + bc + 3 < N) ? B[(size_t)(k0 + br) * N + n0 + bc + 3] : 0.f;
            }
            *(float4*)&Bs[br][bc] = v;
        }
        __syncthreads();
#pragma unroll
        for (int k = 0; k < BKK; k++) {
            float4 a0 = *(float4*)&As[k][ty * 8];
            float4 a1 = *(float4*)&As[k][ty * 8 + 4];
            float4 b4 = *(float4*)&Bs[k][tx * 4];
            float av[8] = {a0.x, a0.y, a0.z, a0.w, a1.x, a1.y, a1.z, a1.w};
            float bv[4] = {b4.x, b4.y, b4.z, b4.w};
#pragma unroll
            for (int i = 0; i < 8; i++)
#pragma unroll
                for (int j = 0; j < 4; j++)
                    acc[i][j] += av[i] * bv[j];
        }
        __syncthreads();
    }

    int nc = n0 + tx * 4;
    if (nc + 3 < N) {
        float4 bv = *(const float4*)(bias + nc);
#pragma unroll
        for (int i = 0; i < 8; i++) {
            int m = m0 + ty * 8 + i;
            float4 o;
            o.x = acc[i][0] + bv.x;
            o.y = acc[i][1] + bv.y;
            o.z = acc[i][2] + bv.z;
            o.w = acc[i][3] + bv.w;
            *(float4*)(C + (size_t)m * N + nc) = o;
        }
    } else {
#pragma unroll
        for (int i = 0; i < 8; i++) {
            int m = m0 + ty * 8 + i;
#pragma unroll
            for (int j = 0; j < 4; j++)
                if (nc + j < N)
                    C[(size_t)m * N + nc + j] = acc[i][j] + bias[nc + j];
        }
    }
}

// ---------------- RMSNorm over first 128 cols of each row ----------------
__global__ void rmsnorm_kernel(float* __restrict__ data, const float* __restrict__ w,
                               int rows, int stride)
{
    int row = blockIdx.x * 8 + (threadIdx.x >> 5);
    int lane = threadIdx.x & 31;
    if (row >= rows) return;
    float* p = data + (size_t)row * stride;
    float4 v = *(float4*)(p + lane * 4);
    float ss = v.x * v.x + v.y * v.y + v.z * v.z + v.w * v.w;
#pragma unroll
    for (int o = 16; o; o >>= 1) ss += __shfl_xor_sync(0xffffffffu, ss, o);
    float sc = rsqrtf(ss * (1.f / 128.f) + 1e-8f);
    float4 wv = *(const float4*)(w + lane * 4);
    v.x *= wv.x * sc;
    v.y *= wv.y * sc;
    v.z *= wv.z * sc;
    v.w *= wv.w * sc;
    *(float4*)(p + lane * 4) = v;
}

// ---------------- pack Q with RoPE (scaled + tf32-rounded) ----------------
__global__ void pack_q_kernel(const float* __restrict__ q, const int* __restrict__ pos,
                              float* __restrict__ qs)
{
    int idx = blockIdx.x * blockDim.x + threadIdx.x;
    if (idx >= BATCH * NH * S_LEN * QDIM) return;
    int d = idx & 127;
    int s = (idx >> 7) & (S_LEN - 1);
    int h = (idx >> 18) & 7;
    int b = idx >> 21;
    int r = b * S_LEN + s;
    float val;
    if (d < Q_NOPE_) {
        val = q[(size_t)r * 1024 + h * Q_NOPE_ + d];
    } else {
        int j = d - Q_NOPE_;
        int jp = j & ~1;
        int i = jp >> 1;
        const float* base = q + (size_t)r * 1024 + NH * Q_NOPE_ + h * Q_ROPE_;
        float xe = base[jp];
        float xo = base[jp + 1];
        float p = (float)pos[r];
        float inv = powf(10000.f, -(float)(2 * i) / (float)Q_ROPE_);
        float ang = p * inv;
        float sn, cs;
        sincosf(ang, &sn, &cs);
        val = (j & 1) ? (xe * sn + xo * cs) : (xe * cs - xo * sn);
    }
    qs[idx] = to_tf32(val * SM_SCALE);
}

// ---------------- pack K with RoPE (tf32-rounded) ----------------
__global__ void pack_k_kernel(const float* __restrict__ kv, const float* __restrict__ ckvkr,
                              const int* __restrict__ pos, float* __restrict__ ks)
{
    int idx = blockIdx.x * blockDim.x + threadIdx.x;
    if (idx >= BATCH * NH * S_LEN * KDIM) return;
    int d = idx & 127;
    int s = (idx >> 7) & (S_LEN - 1);
    int h = (idx >> 18) & 7;
    int b = idx >> 21;
    int r = b * S_LEN + s;
    float val;
    if (d < K_NOPE_) {
        val = kv[(size_t)r * 2560 + h * K_NOPE_ + d];
    } else {
        int j = d - K_NOPE_;
        int jp = j & ~1;
        int i = jp >> 1;
        const float* base = ckvkr + (size_t)r * 192 + KV_C_;
        float xe = base[jp];
        float xo = base[jp + 1];
        float p = (float)pos[r];
        float inv = powf(10000.f, -(float)(2 * i) / (float)K_ROPE_);
        float ang = p * inv;
        float sn, cs;
        sincosf(ang, &sn, &cs);
        val = (j & 1) ? (xe * sn + xo * cs) : (xe * cs - xo * sn);
    }
    ks[idx] = to_tf32(val);
}

// ---------------- pack V (tf32-rounded) ----------------
__global__ void pack_v_kernel(const float* __restrict__ kv, float* __restrict__ vs)
{
    int idx = blockIdx.x * blockDim.x + threadIdx.x;
    if (idx >= BATCH * NH * S_LEN * V_HD_) return;
    int d = idx & 255;
    int s = (idx >> 8) & (S_LEN - 1);
    int h = (idx >> 19) & 7;
    int b = idx >> 22;
    int r = b * S_LEN + s;
    vs[idx] = to_tf32(kv[(size_t)r * 2560 + NH * K_NOPE_ + h * V_HD_ + d]);
}

// ---------------- TF32 tensor-core flash attention ----------------
// CTA: 128 q-rows, 64-key blocks, 512 threads (16 warps = 8 over M x 2 over N/DV).
// smem strides padded so (4*row + col) % 32 covers all banks for fragment loads.
#define QS_STRIDE 132
#define KS_STRIDE 132
#define VS_STRIDE 260
#define PS_STRIDE 68
#define QS_OFF  0
#define KS_OFF  (QS_OFF + 128 * QS_STRIDE)          // 16896
#define VS_OFF  (KS_OFF + 64 * KS_STRIDE)           // 25344
#define PS_OFF  (VS_OFF + 64 * VS_STRIDE)           // 41984
#define STM_OFF (PS_OFF + 128 * PS_STRIDE)          // 50688
#define STS_OFF (STM_OFF + 256)                     // 50944
#define FLASH_SMEM_FLOATS (STS_OFF + 256)           // 51200
#define FLASH_SMEM_BYTES  (FLASH_SMEM_FLOATS * 4)   // 204800

__global__ __launch_bounds__(512, 1)
void flash_mma_kernel(const float* __restrict__ qs, const float* __restrict__ ks,
                      const float* __restrict__ vs, float* __restrict__ attn)
{
    extern __shared__ float sm[];
    float* Qs  = sm + QS_OFF;
    float* Ks  = sm + KS_OFF;
    float* Vs  = sm + VS_OFF;
    float* Ps  = sm + PS_OFF;
    float* StM = sm + STM_OFF;   // [2][128]
    float* StS = sm + STS_OFF;   // [2][128]

    int b = blockIdx.z, h = blockIdx.y, qt = blockIdx.x;
    int tid  = threadIdx.x;
    int wid  = tid >> 5;
    int lane = tid & 31;
    int mw = wid >> 1;           // 0..7
    int nw = wid & 1;            // 0..1
    int g  = lane >> 2;          // groupID 0..7
    int t  = lane & 3;           // thread-in-group

    size_t bh = (size_t)(b * NH + h) * S_LEN;

    // load Q tile once: 128 rows x 128 dims
    {
        const float4* Qg = (const float4*)(qs + (bh + (size_t)qt * 128) * 128);
#pragma unroll
        for (int p = 0; p < 8; p++) {
            int r = wid + p * 16;
            *(float4*)&Qs[r * QS_STRIDE + lane * 4] = Qg[r * 32 + lane];
        }
    }

    int qrow = mw * 16;
    float m0 = -1e30f, m1 = -1e30f, l0 = 0.f, l1 = 0.f;
    float o[16][4];
#pragma unroll
    for (int dt = 0; dt < 16; dt++)
#pragma unroll
        for (int j = 0; j < 4; j++) o[dt][j] = 0.f;

    for (int kt = 0; kt < S_LEN / 64; kt++) {
        __syncthreads();
        // load K (64x128) and V (64x256) tiles
        {
            const float4* Kg = (const float4*)(ks + (bh + (size_t)kt * 64) * 128);
            const float4* Vg = (const float4*)(vs + (bh + (size_t)kt * 64) * 256);
#pragma unroll
            for (int p = 0; p < 4; p++) {
                int r = wid + p * 16;
                *(float4*)&Ks[r * KS_STRIDE + lane * 4] = Kg[r * 32 + lane];
                *(float4*)&Vs[r * VS_STRIDE + lane * 4]       = Vg[r * 64 + lane];
                *(float4*)&Vs[r * VS_STRIDE + 128 + lane * 4] = Vg[r * 64 + 32 + lane];
            }
        }
        __syncthreads();

        // ---- scores: warp computes 16 rows x 32 key-cols ----
        float c[4][4];
#pragma unroll
        for (int nt = 0; nt < 4; nt++)
#pragma unroll
            for (int j = 0; j < 4; j++) c[nt][j] = 0.f;

#pragma unroll
        for (int k8 = 0; k8 < 16; k8++) {
            int kc = k8 * 8;
            uint32_t a0 = __float_as_uint(Qs[(qrow + g) * QS_STRIDE + kc + t]);
            uint32_t a1 = __float_as_uint(Qs[(qrow + g + 8) * QS_STRIDE + kc + t]);
            uint32_t a2 = __float_as_uint(Qs[(qrow + g) * QS_STRIDE + kc + t + 4]);
            uint32_t a3 = __float_as_uint(Qs[(qrow + g + 8) * QS_STRIDE + kc + t + 4]);
#pragma unroll
            for (int nt = 0; nt < 4; nt++) {
                int ncol = nw * 32 + nt * 8 + g;
                uint32_t b0 = __float_as_uint(Ks[ncol * KS_STRIDE + kc + t]);
                uint32_t b1 = __float_as_uint(Ks[ncol * KS_STRIDE + kc + t + 4]);
                mma_tf32(c[nt], a0, a1, a2, a3, b0, b1);
            }
        }

        // ---- online softmax (scale already folded into Q) ----
        float pm0 = -1e30f, pm1 = -1e30f;
#pragma unroll
        for (int nt = 0; nt < 4; nt++) {
            pm0 = fmaxf(pm0, fmaxf(c[nt][0], c[nt][1]));
            pm1 = fmaxf(pm1, fmaxf(c[nt][2], c[nt][3]));
        }
        pm0 = fmaxf(pm0, __shfl_xor_sync(0xffffffffu, pm0, 1));
        pm0 = fmaxf(pm0, __shfl_xor_sync(0xffffffffu, pm0, 2));
        pm1 = fmaxf(pm1, __shfl_xor_sync(0xffffffffu, pm1, 1));
        pm1 = fmaxf(pm1, __shfl_xor_sync(0xffffffffu, pm1, 2));

        float ex[4][4];
        float ps0 = 0.f, ps1 = 0.f;
#pragma unroll
        for (int nt = 0; nt < 4; nt++) {
            ex[nt][0] = __expf(c[nt][0] - pm0);
            ex[nt][1] = __expf(c[nt][1] - pm0);
            ex[nt][2] = __expf(c[nt][2] - pm1);
            ex[nt][3] = __expf(c[nt][3] - pm1);
            ps0 += ex[nt][0] + ex[nt][1];
            ps1 += ex[nt][2] + ex[nt][3];
        }
        ps0 += __shfl_xor_sync(0xffffffffu, ps0, 1);
        ps0 += __shfl_xor_sync(0xffffffffu, ps0, 2);
        ps1 += __shfl_xor_sync(0xffffffffu, ps1, 1);
        ps1 += __shfl_xor_sync(0xffffffffu, ps1, 2);

        if (t == 0) {
            StM[nw * 128 + qrow + g]     = pm0;
            StM[nw * 128 + qrow + g + 8] = pm1;
            StS[nw * 128 + qrow + g]     = ps0;
            StS[nw * 128 + qrow + g + 8] = ps1;
        }
        __syncthreads();

        // combine the two N-halves
        int ow = 1 - nw;
        float pmO0 = StM[ow * 128 + qrow + g];
        float pmO1 = StM[ow * 128 + qrow + g + 8];
        float psO0 = StS[ow * 128 + qrow + g];
        float psO1 = StS[ow * 128 + qrow + g + 8];

        float mn0 = fmaxf(pm0, pmO0);
        float mn1 = fmaxf(pm1, pmO1);
        float rs0 = ps0 * __expf(pm0 - mn0) + psO0 * __expf(pmO0 - mn0);
        float rs1 = ps1 * __expf(pm1 - mn1) + psO1 * __expf(pmO1 - mn1);

        float mnew0 = fmaxf(m0, mn0);
        float mnew1 = fmaxf(m1, mn1);
        float corr0 = __expf(m0 - mnew0);
        float corr1 = __expf(m1 - mnew1);
        l0 = l0 * corr0 + rs0 * __expf(mn0 - mnew0);
        l1 = l1 * corr1 + rs1 * __expf(mn1 - mnew1);
        m0 = mnew0;
        m1 = mnew1;

#pragma unroll
        for (int dt = 0; dt < 16; dt++) {
            o[dt][0] *= corr0;
            o[dt][1] *= corr0;
            o[dt][2] *= corr1;
            o[dt][3] *= corr1;
        }

        // write P (rescaled to the new running max, tf32-rounded)
        float f0 = __expf(pm0 - mnew0);
        float f1 = __expf(pm1 - mnew1);
#pragma unroll
        for (int nt = 0; nt < 4; nt++) {
            int col = nw * 32 + nt * 8 + 2 * t;
            Ps[(qrow + g) * PS_STRIDE + col]         = to_tf32(ex[nt][0] * f0);
            Ps[(qrow + g) * PS_STRIDE + col + 1]     = to_tf32(ex[nt][1] * f0);
            Ps[(qrow + g + 8) * PS_STRIDE + col]     = to_tf32(ex[nt][2] * f1);
            Ps[(qrow + g + 8) * PS_STRIDE + col + 1] = to_tf32(ex[nt][3] * f1);
        }
        __syncthreads();

        // ---- O += P @ V : warp does 16 rows x 128 dv-cols (nw half) ----
#pragma unroll
        for (int k8 = 0; k8 < 8; k8++) {
            int kc = k8 * 8;
            uint32_t a0 = __float_as_uint(Ps[(qrow + g) * PS_STRIDE + kc + t]);
            uint32_t a1 = __float_as_uint(Ps[(qrow + g + 8) * PS_STRIDE + kc + t]);
            uint32_t a2 = __float_as_uint(Ps[(qrow + g) * PS_STRIDE + kc + t + 4]);
            uint32_t a3 = __float_as_uint(Ps[(qrow + g + 8) * PS_STRIDE + kc + t + 4]);
#pragma unroll
            for (int dt = 0; dt < 16; dt++) {
                int dv = nw * 128 + dt * 8 + g;
                uint32_t b0 = __float_as_uint(Vs[(kc + t) * VS_STRIDE + dv]);
                uint32_t b1 = __float_as_uint(Vs[(kc + t + 4) * VS_STRIDE + dv]);
                mma_tf32(o[dt], a0, a1, a2, a3, b0, b1);
            }
        }
    }

    // ---- epilogue: normalize and write attn[b, s, h*256 + dv] ----
    float inv0 = 1.f / l0;
    float inv1 = 1.f / l1;
    int row0 = b * S_LEN + qt * 128 + qrow + g;
    int row1 = row0 + 8;
#pragma unroll
    for (int dt = 0; dt < 16; dt++) {
        int col = h * V_HD_ + nw * 128 + dt * 8 + 2 * t;
        float2 v0 = make_float2(o[dt][0] * inv0, o[dt][1] * inv0);
        float2 v1 = make_float2(o[dt][2] * inv1, o[dt][3] * inv1);
        *(float2*)(attn + (size_t)row0 * (NH * V_HD_) + col) = v0;
        *(float2*)(attn + (size_t)row1 * (NH * V_HD_) + col) = v1;
    }
}

// ---------------- host launcher ----------------
extern "C" void kernel_launch(void* const* d_in, const int* in_sizes, int n_in,
                              void* d_out, int out_size)
{
    const float* x         = (const float*)d_in[0];
    const int*   pos       = (const int*)  d_in[1];
    const float* w_dq_w    = (const float*)d_in[2];
    const float* w_dq_b    = (const float*)d_in[3];
    const float* q_norm_w  = (const float*)d_in[4];
    const float* w_uq_qr_w = (const float*)d_in[5];
    const float* w_uq_qr_b = (const float*)d_in[6];
    const float* w_dkv_kr_w= (const float*)d_in[7];
    const float* w_dkv_kr_b= (const float*)d_in[8];
    const float* kv_norm_w = (const float*)d_in[9];
    const float* w_uk_uv_w = (const float*)d_in[10];
    const float* w_uk_uv_b = (const float*)d_in[11];
    const float* w_o_w     = (const float*)d_in[12];
    const float* w_o_b     = (const float*)d_in[13];
    float* out = (float*)d_out;

    float *cq, *ckvkr, *q, *kv, *qsb, *ksb, *vsb, *attn;
    cudaGetSymbolAddress((void**)&cq,    g_cq);
    cudaGetSymbolAddress((void**)&ckvkr, g_ckvkr);
    cudaGetSymbolAddress((void**)&q,     g_q);
    cudaGetSymbolAddress((void**)&kv,    g_kv);
    cudaGetSymbolAddress((void**)&qsb,   g_qs);
    cudaGetSymbolAddress((void**)&ksb,   g_ks);
    cudaGetSymbolAddress((void**)&vsb,   g_vs);
    cudaGetSymbolAddress((void**)&attn,  g_attn);

    cudaFuncSetAttribute(flash_mma_kernel, cudaFuncAttributeMaxDynamicSharedMemorySize,
                         FLASH_SMEM_BYTES);

    dim3 blk(256);

    gemm_bias_kernel<<<dim3(128 / BN, NROWS / BM), blk>>>(x, DIM_, w_dq_w, w_dq_b, cq,
                                                          NROWS, 128, DIM_);
    rmsnorm_kernel<<<NROWS / 8, 256>>>(cq, q_norm_w, NROWS, 128);

    gemm_bias_kernel<<<dim3(192 / BN, NROWS / BM), blk>>>(x, DIM_, w_dkv_kr_w, w_dkv_kr_b,
                                                          ckvkr, NROWS, 192, DIM_);
    rmsnorm_kernel<<<NROWS / 8, 256>>>(ckvkr, kv_norm_w, NROWS, 192);

    gemm_bias_kernel<<<dim3(1024 / BN, NROWS / BM), blk>>>(cq, 128, w_uq_qr_w, w_uq_qr_b,
                                                           q, NROWS, 1024, 128);

    gemm_bias_kernel<<<dim3(2560 / BN, NROWS / BM), blk>>>(ckvkr, 192, w_uk_uv_w, w_uk_uv_b,
                                                           kv, NROWS, 2560, 128);

    pack_q_kernel<<<(BATCH * NH * S_LEN * QDIM) / 256, 256>>>(q, pos, qsb);
    pack_k_kernel<<<(BATCH * NH * S_LEN * KDIM) / 256, 256>>>(kv, ckvkr, pos, ksb);
    pack_v_kernel<<<(BATCH * NH * S_LEN * V_HD_) / 256, 256>>>(kv, vsb);

    flash_mma_kernel<<<dim3(S_LEN / 128, NH, BATCH), 512, FLASH_SMEM_BYTES>>>(qsb, ksb, vsb, attn);

    gemm_bias_kernel<<<dim3(1024 / BN, NROWS / BM), blk>>>(attn, NH * V_HD_, w_o_w, w_o_b,
                                                           out, NROWS, 1024, NH * V_HD_);
}

// round 3
// speedup vs baseline: 3.7934x; 1.5944x over previous
#include <cuda_runtime.h>
#include <math.h>
#include <stdint.h>

// ---------------- problem constants ----------------
#define BATCH   2
#define S_LEN   2048
#define NROWS   (BATCH * S_LEN)     // 4096
#define DIM_    1024
#define NH      8
#define Q_C_    128
#define Q_NOPE_ 96
#define Q_ROPE_ 32
#define KV_C_   128
#define K_NOPE_ 64
#define K_ROPE_ 64
#define V_HD_   256
#define QDIM    128
#define KDIM    128
#define SM_SCALE 0.08838834764831845f   // 1/sqrt(128)

// ---------------- scratch (static device arrays; no allocations) ----------------
__device__ float g_cq   [(size_t)NROWS * Q_C_];
__device__ float g_ckvkr[(size_t)NROWS * 192];
__device__ float g_q    [(size_t)NROWS * 1024];
__device__ float g_kv   [(size_t)NROWS * 2560];
__device__ float g_qs   [(size_t)BATCH * NH * S_LEN * QDIM];
__device__ float g_ks   [(size_t)BATCH * NH * S_LEN * KDIM];
__device__ float g_vs   [(size_t)BATCH * NH * S_LEN * V_HD_];
__device__ float g_attn [(size_t)NROWS * (NH * V_HD_)];
// tf32-rounded copies of GEMM operands
__device__ float g_x32  [(size_t)NROWS * DIM_];
__device__ float g_w1   [(size_t)DIM_ * Q_C_];          // w_dq_w
__device__ float g_w2   [(size_t)Q_C_ * 1024];          // w_uq_qr_w
__device__ float g_w3   [(size_t)DIM_ * 192];           // w_dkv_kr_w
__device__ float g_w4   [(size_t)KV_C_ * 2560];         // w_uk_uv_w
__device__ float g_w5   [(size_t)2048 * DIM_];          // w_o_w

// ---------------- helpers ----------------
__device__ __forceinline__ float to_tf32(float x) {
    uint32_t u;
    asm("cvt.rna.tf32.f32 %0, %1;" : "=r"(u) : "f"(x));
    return __uint_as_float(u);
}

__device__ __forceinline__ void mma_tf32(float* c, uint32_t a0, uint32_t a1,
                                         uint32_t a2, uint32_t a3,
                                         uint32_t b0, uint32_t b1) {
    asm volatile(
        "mma.sync.aligned.m16n8k8.row.col.f32.tf32.tf32.f32 "
        "{%0,%1,%2,%3}, {%4,%5,%6,%7}, {%8,%9}, {%0,%1,%2,%3};"
        : "+f"(c[0]), "+f"(c[1]), "+f"(c[2]), "+f"(c[3])
        : "r"(a0), "r"(a1), "r"(a2), "r"(a3), "r"(b0), "r"(b1));
}

__device__ __forceinline__ void cp_async16(void* smem_ptr, const void* gptr) {
    uint32_t s = (uint32_t)__cvta_generic_to_shared(smem_ptr);
    asm volatile("cp.async.cg.shared.global [%0], [%1], 16;" :: "r"(s), "l"(gptr));
}
#define CP_COMMIT() asm volatile("cp.async.commit_group;")
#define CP_WAIT(n)  asm volatile("cp.async.wait_group %0;" :: "n"(n))

// ---------------- tf32 rounding pass ----------------
__global__ void round_tf32_kernel(const float* __restrict__ in, float* __restrict__ out, int n)
{
    int i = (blockIdx.x * blockDim.x + threadIdx.x) * 4;
    if (i >= n) return;
    float4 v = *(const float4*)(in + i);
    v.x = to_tf32(v.x); v.y = to_tf32(v.y);
    v.z = to_tf32(v.z); v.w = to_tf32(v.w);
    *(float4*)(out + i) = v;
}

// ---------------- TF32 tensor-core GEMM: C = A(lda) @ B + bias ----------------
// BM=128, BN=64, BK=32, 256 threads, 8 warps = 4(M) x 2(N), warp tile 32x32.
// A and B must be pre-rounded to tf32. Double-buffered cp.async pipeline.
#define GBM 128
#define GBN 64
#define GBK 32
#define AS_STRIDE 36
#define BS_STRIDE 72
#define ABUF (GBM * AS_STRIDE)                 // 4608 floats
#define BBUF (GBK * BS_STRIDE)                 // 2304 floats
#define GEMM_SMEM_FLOATS (2 * (ABUF + BBUF))   // 13824
#define GEMM_SMEM_BYTES  (GEMM_SMEM_FLOATS * 4)

__global__ __launch_bounds__(256, 2)
void gemm_tf32_kernel(const float* __restrict__ A, int lda,
                      const float* __restrict__ B,
                      const float* __restrict__ bias,
                      float* __restrict__ C,
                      int M, int N, int K)
{
    extern __shared__ float sm[];
    int tid  = threadIdx.x;
    int wid  = tid >> 5;
    int lane = tid & 31;
    int wm = wid >> 1;          // 0..3
    int wn = wid & 1;           // 0..1
    int g  = lane >> 2;
    int t  = lane & 3;
    int m0 = blockIdx.y * GBM;
    int n0 = blockIdx.x * GBN;

    float acc[2][4][4];
#pragma unroll
    for (int mi = 0; mi < 2; mi++)
#pragma unroll
        for (int ni = 0; ni < 4; ni++)
#pragma unroll
            for (int j = 0; j < 4; j++) acc[mi][ni][j] = 0.f;

    int nk = K / GBK;

    // stage loader
    auto load_tile = [&](int kt, int buf) {
        float* As = sm + buf * (ABUF + BBUF);
        float* Bs = As + ABUF;
        int k0 = kt * GBK;
#pragma unroll
        for (int p = 0; p < 4; p++) {           // A: 128x32 = 1024 float4
            int idx = tid + p * 256;
            int r = idx >> 3, c = (idx & 7) * 4;
            cp_async16(&As[r * AS_STRIDE + c],
                       A + (size_t)(m0 + r) * lda + k0 + c);
        }
#pragma unroll
        for (int p = 0; p < 2; p++) {           // B: 32x64 = 512 float4
            int idx = tid + p * 256;
            int r = idx >> 4, c = (idx & 15) * 4;
            cp_async16(&Bs[r * BS_STRIDE + c],
                       B + (size_t)(k0 + r) * N + n0 + c);
        }
        CP_COMMIT();
    };

    load_tile(0, 0);

    for (int kt = 0; kt < nk; kt++) {
        int buf = kt & 1;
        if (kt + 1 < nk) {
            load_tile(kt + 1, buf ^ 1);
            CP_WAIT(1);
        } else {
            CP_WAIT(0);
        }
        __syncthreads();

        const float* As = sm + buf * (ABUF + BBUF);
        const float* Bs = As + ABUF;

#pragma unroll
        for (int k8 = 0; k8 < 4; k8++) {
            int kc = k8 * 8;
            uint32_t a[2][4];
#pragma unroll
            for (int mi = 0; mi < 2; mi++) {
                int row = wm * 32 + mi * 16;
                a[mi][0] = __float_as_uint(As[(row + g) * AS_STRIDE + kc + t]);
                a[mi][1] = __float_as_uint(As[(row + g + 8) * AS_STRIDE + kc + t]);
                a[mi][2] = __float_as_uint(As[(row + g) * AS_STRIDE + kc + t + 4]);
                a[mi][3] = __float_as_uint(As[(row + g + 8) * AS_STRIDE + kc + t + 4]);
            }
#pragma unroll
            for (int ni = 0; ni < 4; ni++) {
                int col = wn * 32 + ni * 8 + g;
                uint32_t b0 = __float_as_uint(Bs[(kc + t) * BS_STRIDE + col]);
                uint32_t b1 = __float_as_uint(Bs[(kc + t + 4) * BS_STRIDE + col]);
                mma_tf32(acc[0][ni], a[0][0], a[0][1], a[0][2], a[0][3], b0, b1);
                mma_tf32(acc[1][ni], a[1][0], a[1][1], a[1][2], a[1][3], b0, b1);
            }
        }
        __syncthreads();
    }

    // epilogue: add bias, store fp32
#pragma unroll
    for (int ni = 0; ni < 4; ni++) {
        int col = n0 + wn * 32 + ni * 8 + 2 * t;
        float2 bv = *(const float2*)(bias + col);
#pragma unroll
        for (int mi = 0; mi < 2; mi++) {
            int r0 = m0 + wm * 32 + mi * 16 + g;
            float2 v0 = make_float2(acc[mi][ni][0] + bv.x, acc[mi][ni][1] + bv.y);
            float2 v1 = make_float2(acc[mi][ni][2] + bv.x, acc[mi][ni][3] + bv.y);
            *(float2*)(C + (size_t)r0 * N + col) = v0;
            *(float2*)(C + (size_t)(r0 + 8) * N + col) = v1;
        }
    }
}

// ---------------- RMSNorm over first 128 cols (stores tf32-rounded) ----------------
__global__ void rmsnorm_kernel(float* __restrict__ data, const float* __restrict__ w,
                               int rows, int stride)
{
    int row = blockIdx.x * 8 + (threadIdx.x >> 5);
    int lane = threadIdx.x & 31;
    if (row >= rows) return;
    float* p = data + (size_t)row * stride;
    float4 v = *(float4*)(p + lane * 4);
    float ss = v.x * v.x + v.y * v.y + v.z * v.z + v.w * v.w;
#pragma unroll
    for (int o = 16; o; o >>= 1) ss += __shfl_xor_sync(0xffffffffu, ss, o);
    float sc = rsqrtf(ss * (1.f / 128.f) + 1e-8f);
    float4 wv = *(const float4*)(w + lane * 4);
    v.x = to_tf32(v.x * wv.x * sc);
    v.y = to_tf32(v.y * wv.y * sc);
    v.z = to_tf32(v.z * wv.z * sc);
    v.w = to_tf32(v.w * wv.w * sc);
    *(float4*)(p + lane * 4) = v;
}

// ---------------- pack Q with RoPE (scaled + tf32-rounded) ----------------
__global__ void pack_q_kernel(const float* __restrict__ q, const int* __restrict__ pos,
                              float* __restrict__ qs)
{
    int idx = blockIdx.x * blockDim.x + threadIdx.x;
    if (idx >= BATCH * NH * S_LEN * QDIM) return;
    int d = idx & 127;
    int s = (idx >> 7) & (S_LEN - 1);
    int h = (idx >> 18) & 7;
    int b = idx >> 21;
    int r = b * S_LEN + s;
    float val;
    if (d < Q_NOPE_) {
        val = q[(size_t)r * 1024 + h * Q_NOPE_ + d];
    } else {
        int j = d - Q_NOPE_;
        int jp = j & ~1;
        int i = jp >> 1;
        const float* base = q + (size_t)r * 1024 + NH * Q_NOPE_ + h * Q_ROPE_;
        float xe = base[jp];
        float xo = base[jp + 1];
        float p = (float)pos[r];
        float inv = powf(10000.f, -(float)(2 * i) / (float)Q_ROPE_);
        float ang = p * inv;
        float sn, cs;
        sincosf(ang, &sn, &cs);
        val = (j & 1) ? (xe * sn + xo * cs) : (xe * cs - xo * sn);
    }
    qs[idx] = to_tf32(val * SM_SCALE);
}

// ---------------- pack K with RoPE (tf32-rounded) ----------------
__global__ void pack_k_kernel(const float* __restrict__ kv, const float* __restrict__ ckvkr,
                              const int* __restrict__ pos, float* __restrict__ ks)
{
    int idx = blockIdx.x * blockDim.x + threadIdx.x;
    if (idx >= BATCH * NH * S_LEN * KDIM) return;
    int d = idx & 127;
    int s = (idx >> 7) & (S_LEN - 1);
    int h = (idx >> 18) & 7;
    int b = idx >> 21;
    int r = b * S_LEN + s;
    float val;
    if (d < K_NOPE_) {
        val = kv[(size_t)r * 2560 + h * K_NOPE_ + d];
    } else {
        int j = d - K_NOPE_;
        int jp = j & ~1;
        int i = jp >> 1;
        const float* base = ckvkr + (size_t)r * 192 + KV_C_;
        float xe = base[jp];
        float xo = base[jp + 1];
        float p = (float)pos[r];
        float inv = powf(10000.f, -(float)(2 * i) / (float)K_ROPE_);
        float ang = p * inv;
        float sn, cs;
        sincosf(ang, &sn, &cs);
        val = (j & 1) ? (xe * sn + xo * cs) : (xe * cs - xo * sn);
    }
    ks[idx] = to_tf32(val);
}

// ---------------- pack V (tf32-rounded) ----------------
__global__ void pack_v_kernel(const float* __restrict__ kv, float* __restrict__ vs)
{
    int idx = blockIdx.x * blockDim.x + threadIdx.x;
    if (idx >= BATCH * NH * S_LEN * V_HD_) return;
    int d = idx & 255;
    int s = (idx >> 8) & (S_LEN - 1);
    int h = (idx >> 19) & 7;
    int b = idx >> 22;
    int r = b * S_LEN + s;
    vs[idx] = to_tf32(kv[(size_t)r * 2560 + NH * K_NOPE_ + h * V_HD_ + d]);
}

// ---------------- TF32 tensor-core flash attention ----------------
#define QS_STRIDE 132
#define KS_STRIDE 132
#define VS_STRIDE 260
#define PS_STRIDE 68
#define QS_OFF  0
#define KS_OFF  (QS_OFF + 128 * QS_STRIDE)
#define VS_OFF  (KS_OFF + 64 * KS_STRIDE)
#define PS_OFF  (VS_OFF + 64 * VS_STRIDE)
#define STM_OFF (PS_OFF + 128 * PS_STRIDE)
#define STS_OFF (STM_OFF + 256)
#define FLASH_SMEM_FLOATS (STS_OFF + 256)
#define FLASH_SMEM_BYTES  (FLASH_SMEM_FLOATS * 4)

__global__ __launch_bounds__(512, 1)
void flash_mma_kernel(const float* __restrict__ qs, const float* __restrict__ ks,
                      const float* __restrict__ vs, float* __restrict__ attn)
{
    extern __shared__ float sm[];
    float* Qs  = sm + QS_OFF;
    float* Ks  = sm + KS_OFF;
    float* Vs  = sm + VS_OFF;
    float* Ps  = sm + PS_OFF;
    float* StM = sm + STM_OFF;
    float* StS = sm + STS_OFF;

    int b = blockIdx.z, h = blockIdx.y, qt = blockIdx.x;
    int tid  = threadIdx.x;
    int wid  = tid >> 5;
    int lane = tid & 31;
    int mw = wid >> 1;
    int nw = wid & 1;
    int g  = lane >> 2;
    int t  = lane & 3;

    size_t bh = (size_t)(b * NH + h) * S_LEN;

    {
        const float4* Qg = (const float4*)(qs + (bh + (size_t)qt * 128) * 128);
#pragma unroll
        for (int p = 0; p < 8; p++) {
            int r = wid + p * 16;
            *(float4*)&Qs[r * QS_STRIDE + lane * 4] = Qg[r * 32 + lane];
        }
    }

    int qrow = mw * 16;
    float m0 = -1e30f, m1 = -1e30f, l0 = 0.f, l1 = 0.f;
    float o[16][4];
#pragma unroll
    for (int dt = 0; dt < 16; dt++)
#pragma unroll
        for (int j = 0; j < 4; j++) o[dt][j] = 0.f;

    for (int kt = 0; kt < S_LEN / 64; kt++) {
        __syncthreads();
        {
            const float4* Kg = (const float4*)(ks + (bh + (size_t)kt * 64) * 128);
            const float4* Vg = (const float4*)(vs + (bh + (size_t)kt * 64) * 256);
#pragma unroll
            for (int p = 0; p < 4; p++) {
                int r = wid + p * 16;
                *(float4*)&Ks[r * KS_STRIDE + lane * 4] = Kg[r * 32 + lane];
                *(float4*)&Vs[r * VS_STRIDE + lane * 4]       = Vg[r * 64 + lane];
                *(float4*)&Vs[r * VS_STRIDE + 128 + lane * 4] = Vg[r * 64 + 32 + lane];
            }
        }
        __syncthreads();

        float c[4][4];
#pragma unroll
        for (int nt = 0; nt < 4; nt++)
#pragma unroll
            for (int j = 0; j < 4; j++) c[nt][j] = 0.f;

#pragma unroll
        for (int k8 = 0; k8 < 16; k8++) {
            int kc = k8 * 8;
            uint32_t a0 = __float_as_uint(Qs[(qrow + g) * QS_STRIDE + kc + t]);
            uint32_t a1 = __float_as_uint(Qs[(qrow + g + 8) * QS_STRIDE + kc + t]);
            uint32_t a2 = __float_as_uint(Qs[(qrow + g) * QS_STRIDE + kc + t + 4]);
            uint32_t a3 = __float_as_uint(Qs[(qrow + g + 8) * QS_STRIDE + kc + t + 4]);
#pragma unroll
            for (int nt = 0; nt < 4; nt++) {
                int ncol = nw * 32 + nt * 8 + g;
                uint32_t b0 = __float_as_uint(Ks[ncol * KS_STRIDE + kc + t]);
                uint32_t b1 = __float_as_uint(Ks[ncol * KS_STRIDE + kc + t + 4]);
                mma_tf32(c[nt], a0, a1, a2, a3, b0, b1);
            }
        }

        float pm0 = -1e30f, pm1 = -1e30f;
#pragma unroll
        for (int nt = 0; nt < 4; nt++) {
            pm0 = fmaxf(pm0, fmaxf(c[nt][0], c[nt][1]));
            pm1 = fmaxf(pm1, fmaxf(c[nt][2], c[nt][3]));
        }
        pm0 = fmaxf(pm0, __shfl_xor_sync(0xffffffffu, pm0, 1));
        pm0 = fmaxf(pm0, __shfl_xor_sync(0xffffffffu, pm0, 2));
        pm1 = fmaxf(pm1, __shfl_xor_sync(0xffffffffu, pm1, 1));
        pm1 = fmaxf(pm1, __shfl_xor_sync(0xffffffffu, pm1, 2));

        float ex[4][4];
        float ps0 = 0.f, ps1 = 0.f;
#pragma unroll
        for (int nt = 0; nt < 4; nt++) {
            ex[nt][0] = __expf(c[nt][0] - pm0);
            ex[nt][1] = __expf(c[nt][1] - pm0);
            ex[nt][2] = __expf(c[nt][2] - pm1);
            ex[nt][3] = __expf(c[nt][3] - pm1);
            ps0 += ex[nt][0] + ex[nt][1];
            ps1 += ex[nt][2] + ex[nt][3];
        }
        ps0 += __shfl_xor_sync(0xffffffffu, ps0, 1);
        ps0 += __shfl_xor_sync(0xffffffffu, ps0, 2);
        ps1 += __shfl_xor_sync(0xffffffffu, ps1, 1);
        ps1 += __shfl_xor_sync(0xffffffffu, ps1, 2);

        if (t == 0) {
            StM[nw * 128 + qrow + g]     = pm0;
            StM[nw * 128 + qrow + g + 8] = pm1;
            StS[nw * 128 + qrow + g]     = ps0;
            StS[nw * 128 + qrow + g + 8] = ps1;
        }
        __syncthreads();

        int ow = 1 - nw;
        float pmO0 = StM[ow * 128 + qrow + g];
        float pmO1 = StM[ow * 128 + qrow + g + 8];
        float psO0 = StS[ow * 128 + qrow + g];
        float psO1 = StS[ow * 128 + qrow + g + 8];

        float mn0 = fmaxf(pm0, pmO0);
        float mn1 = fmaxf(pm1, pmO1);
        float rs0 = ps0 * __expf(pm0 - mn0) + psO0 * __expf(pmO0 - mn0);
        float rs1 = ps1 * __expf(pm1 - mn1) + psO1 * __expf(pmO1 - mn1);

        float mnew0 = fmaxf(m0, mn0);
        float mnew1 = fmaxf(m1, mn1);
        float corr0 = __expf(m0 - mnew0);
        float corr1 = __expf(m1 - mnew1);
        l0 = l0 * corr0 + rs0 * __expf(mn0 - mnew0);
        l1 = l1 * corr1 + rs1 * __expf(mn1 - mnew1);
        m0 = mnew0;
        m1 = mnew1;

#pragma unroll
        for (int dt = 0; dt < 16; dt++) {
            o[dt][0] *= corr0;
            o[dt][1] *= corr0;
            o[dt][2] *= corr1;
            o[dt][3] *= corr1;
        }

        float f0 = __expf(pm0 - mnew0);
        float f1 = __expf(pm1 - mnew1);
#pragma unroll
        for (int nt = 0; nt < 4; nt++) {
            int col = nw * 32 + nt * 8 + 2 * t;
            Ps[(qrow + g) * PS_STRIDE + col]         = to_tf32(ex[nt][0] * f0);
            Ps[(qrow + g) * PS_STRIDE + col + 1]     = to_tf32(ex[nt][1] * f0);
            Ps[(qrow + g + 8) * PS_STRIDE + col]     = to_tf32(ex[nt][2] * f1);
            Ps[(qrow + g + 8) * PS_STRIDE + col + 1] = to_tf32(ex[nt][3] * f1);
        }
        __syncthreads();

#pragma unroll
        for (int k8 = 0; k8 < 8; k8++) {
            int kc = k8 * 8;
            uint32_t a0 = __float_as_uint(Ps[(qrow + g) * PS_STRIDE + kc + t]);
            uint32_t a1 = __float_as_uint(Ps[(qrow + g + 8) * PS_STRIDE + kc + t]);
            uint32_t a2 = __float_as_uint(Ps[(qrow + g) * PS_STRIDE + kc + t + 4]);
            uint32_t a3 = __float_as_uint(Ps[(qrow + g + 8) * PS_STRIDE + kc + t + 4]);
#pragma unroll
            for (int dt = 0; dt < 16; dt++) {
                int dv = nw * 128 + dt * 8 + g;
                uint32_t b0 = __float_as_uint(Vs[(kc + t) * VS_STRIDE + dv]);
                uint32_t b1 = __float_as_uint(Vs[(kc + t + 4) * VS_STRIDE + dv]);
                mma_tf32(o[dt], a0, a1, a2, a3, b0, b1);
            }
        }
    }

    // epilogue: normalize, round to tf32 (feeds the w_o tf32 GEMM), write
    float inv0 = 1.f / l0;
    float inv1 = 1.f / l1;
    int row0 = b * S_LEN + qt * 128 + qrow + g;
    int row1 = row0 + 8;
#pragma unroll
    for (int dt = 0; dt < 16; dt++) {
        int col = h * V_HD_ + nw * 128 + dt * 8 + 2 * t;
        float2 v0 = make_float2(to_tf32(o[dt][0] * inv0), to_tf32(o[dt][1] * inv0));
        float2 v1 = make_float2(to_tf32(o[dt][2] * inv1), to_tf32(o[dt][3] * inv1));
        *(float2*)(attn + (size_t)row0 * (NH * V_HD_) + col) = v0;
        *(float2*)(attn + (size_t)row1 * (NH * V_HD_) + col) = v1;
    }
}

// ---------------- host launcher ----------------
extern "C" void kernel_launch(void* const* d_in, const int* in_sizes, int n_in,
                              void* d_out, int out_size)
{
    const float* x         = (const float*)d_in[0];
    const int*   pos       = (const int*)  d_in[1];
    const float* w_dq_w    = (const float*)d_in[2];
    const float* w_dq_b    = (const float*)d_in[3];
    const float* q_norm_w  = (const float*)d_in[4];
    const float* w_uq_qr_w = (const float*)d_in[5];
    const float* w_uq_qr_b = (const float*)d_in[6];
    const float* w_dkv_kr_w= (const float*)d_in[7];
    const float* w_dkv_kr_b= (const float*)d_in[8];
    const float* kv_norm_w = (const float*)d_in[9];
    const float* w_uk_uv_w = (const float*)d_in[10];
    const float* w_uk_uv_b = (const float*)d_in[11];
    const float* w_o_w     = (const float*)d_in[12];
    const float* w_o_b     = (const float*)d_in[13];
    float* out = (float*)d_out;

    float *cq, *ckvkr, *q, *kv, *qsb, *ksb, *vsb, *attn;
    float *x32, *w1, *w2, *w3, *w4, *w5;
    cudaGetSymbolAddress((void**)&cq,    g_cq);
    cudaGetSymbolAddress((void**)&ckvkr, g_ckvkr);
    cudaGetSymbolAddress((void**)&q,     g_q);
    cudaGetSymbolAddress((void**)&kv,    g_kv);
    cudaGetSymbolAddress((void**)&qsb,   g_qs);
    cudaGetSymbolAddress((void**)&ksb,   g_ks);
    cudaGetSymbolAddress((void**)&vsb,   g_vs);
    cudaGetSymbolAddress((void**)&attn,  g_attn);
    cudaGetSymbolAddress((void**)&x32,   g_x32);
    cudaGetSymbolAddress((void**)&w1,    g_w1);
    cudaGetSymbolAddress((void**)&w2,    g_w2);
    cudaGetSymbolAddress((void**)&w3,    g_w3);
    cudaGetSymbolAddress((void**)&w4,    g_w4);
    cudaGetSymbolAddress((void**)&w5,    g_w5);

    cudaFuncSetAttribute(flash_mma_kernel, cudaFuncAttributeMaxDynamicSharedMemorySize,
                         FLASH_SMEM_BYTES);
    cudaFuncSetAttribute(gemm_tf32_kernel, cudaFuncAttributeMaxDynamicSharedMemorySize,
                         GEMM_SMEM_BYTES);

    // round GEMM operands to tf32
    round_tf32_kernel<<<(NROWS * DIM_) / 1024, 256>>>(x, x32, NROWS * DIM_);
    round_tf32_kernel<<<(DIM_ * Q_C_) / 1024, 256>>>(w_dq_w, w1, DIM_ * Q_C_);
    round_tf32_kernel<<<(Q_C_ * 1024) / 1024, 256>>>(w_uq_qr_w, w2, Q_C_ * 1024);
    round_tf32_kernel<<<(DIM_ * 192) / 1024, 256>>>(w_dkv_kr_w, w3, DIM_ * 192);
    round_tf32_kernel<<<(KV_C_ * 2560) / 1024, 256>>>(w_uk_uv_w, w4, KV_C_ * 2560);
    round_tf32_kernel<<<(2048 * DIM_) / 1024, 256>>>(w_o_w, w5, 2048 * DIM_);

    dim3 blk(256);

    gemm_tf32_kernel<<<dim3(128 / GBN, NROWS / GBM), blk, GEMM_SMEM_BYTES>>>(
        x32, DIM_, w1, w_dq_b, cq, NROWS, 128, DIM_);
    rmsnorm_kernel<<<NROWS / 8, 256>>>(cq, q_norm_w, NROWS, 128);

    gemm_tf32_kernel<<<dim3(192 / GBN, NROWS / GBM), blk, GEMM_SMEM_BYTES>>>(
        x32, DIM_, w3, w_dkv_kr_b, ckvkr, NROWS, 192, DIM_);
    rmsnorm_kernel<<<NROWS / 8, 256>>>(ckvkr, kv_norm_w, NROWS, 192);

    gemm_tf32_kernel<<<dim3(1024 / GBN, NROWS / GBM), blk, GEMM_SMEM_BYTES>>>(
        cq, 128, w2, w_uq_qr_b, q, NROWS, 1024, 128);

    gemm_tf32_kernel<<<dim3(2560 / GBN, NROWS / GBM), blk, GEMM_SMEM_BYTES>>>(
        ckvkr, 192, w4, w_uk_uv_b, kv, NROWS, 2560, 128);

    pack_q_kernel<<<(BATCH * NH * S_LEN * QDIM) / 256, 256>>>(q, pos, qsb);
    pack_k_kernel<<<(BATCH * NH * S_LEN * KDIM) / 256, 256>>>(kv, ckvkr, pos, ksb);
    pack_v_kernel<<<(BATCH * NH * S_LEN * V_HD_) / 256, 256>>>(kv, vsb);

    flash_mma_kernel<<<dim3(S_LEN / 128, NH, BATCH), 512, FLASH_SMEM_BYTES>>>(qsb, ksb, vsb, attn);

    gemm_tf32_kernel<<<dim3(1024 / GBN, NROWS / GBM), blk, GEMM_SMEM_BYTES>>>(
        attn, NH * V_HD_, w5, w_o_b, out, NROWS, 1024, 2048);
}

// round 4
// speedup vs baseline: 3.9457x; 1.0402x over previous
#include <cuda_runtime.h>
#include <math.h>
#include <stdint.h>

// ---------------- problem constants ----------------
#define BATCH   2
#define S_LEN   2048
#define NROWS   (BATCH * S_LEN)     // 4096
#define DIM_    1024
#define NH      8
#define Q_C_    128
#define Q_NOPE_ 96
#define Q_ROPE_ 32
#define KV_C_   128
#define K_NOPE_ 64
#define K_ROPE_ 64
#define V_HD_   256
#define QDIM    128
#define KDIM    128
#define SM_SCALE 0.08838834764831845f   // 1/sqrt(128)

// ---------------- scratch (static device arrays; no allocations) ----------------
__device__ float g_cq   [(size_t)NROWS * Q_C_];
__device__ float g_ckvkr[(size_t)NROWS * 192];
__device__ float g_q    [(size_t)NROWS * 1024];
__device__ float g_kv   [(size_t)NROWS * 2560];
__device__ float g_qs   [(size_t)BATCH * NH * S_LEN * QDIM];
__device__ float g_ks   [(size_t)BATCH * NH * S_LEN * KDIM];
__device__ float g_vs   [(size_t)BATCH * NH * S_LEN * V_HD_];
__device__ float g_attn [(size_t)NROWS * (NH * V_HD_)];
// tf32-rounded copies of GEMM operands
__device__ float g_x32  [(size_t)NROWS * DIM_];
__device__ float g_w1   [(size_t)DIM_ * Q_C_];
__device__ float g_w2   [(size_t)Q_C_ * 1024];
__device__ float g_w3   [(size_t)DIM_ * 192];
__device__ float g_w4   [(size_t)KV_C_ * 2560];
__device__ float g_w5   [(size_t)2048 * DIM_];

// ---------------- helpers ----------------
__device__ __forceinline__ float to_tf32(float x) {
    uint32_t u;
    asm("cvt.rna.tf32.f32 %0, %1;" : "=r"(u) : "f"(x));
    return __uint_as_float(u);
}

__device__ __forceinline__ void mma_tf32(float* c, uint32_t a0, uint32_t a1,
                                         uint32_t a2, uint32_t a3,
                                         uint32_t b0, uint32_t b1) {
    asm volatile(
        "mma.sync.aligned.m16n8k8.row.col.f32.tf32.tf32.f32 "
        "{%0,%1,%2,%3}, {%4,%5,%6,%7}, {%8,%9}, {%0,%1,%2,%3};"
        : "+f"(c[0]), "+f"(c[1]), "+f"(c[2]), "+f"(c[3])
        : "r"(a0), "r"(a1), "r"(a2), "r"(a3), "r"(b0), "r"(b1));
}

__device__ __forceinline__ void cp_async16(void* smem_ptr, const void* gptr) {
    uint32_t s = (uint32_t)__cvta_generic_to_shared(smem_ptr);
    asm volatile("cp.async.cg.shared.global [%0], [%1], 16;" :: "r"(s), "l"(gptr));
}
#define CP_COMMIT() asm volatile("cp.async.commit_group;")
#define CP_WAIT0()  asm volatile("cp.async.wait_group 0;")
#define CP_WAIT1()  asm volatile("cp.async.wait_group 1;")

// ---------------- fused tf32 rounding pass over all GEMM operands ----------------
#define RA_C0 1048576                       // x      (4096*1024/4)
#define RA_C1 (RA_C0 + 32768)               // w1
#define RA_C2 (RA_C1 + 32768)               // w2
#define RA_C3 (RA_C2 + 49152)               // w3
#define RA_C4 (RA_C3 + 81920)               // w4
#define RA_C5 (RA_C4 + 524288)              // w5  -> total 1769472 float4s

__global__ __launch_bounds__(256)
void round_all_kernel(const float* __restrict__ x,  float* __restrict__ ox,
                      const float* __restrict__ a1, float* __restrict__ o1,
                      const float* __restrict__ a2, float* __restrict__ o2,
                      const float* __restrict__ a3, float* __restrict__ o3,
                      const float* __restrict__ a4, float* __restrict__ o4,
                      const float* __restrict__ a5, float* __restrict__ o5)
{
    int i = blockIdx.x * 256 + threadIdx.x;
    const float4* src;
    float4* dst;
    int off;
    if (i < RA_C0)      { src = (const float4*)x;  dst = (float4*)ox; off = i; }
    else if (i < RA_C1) { src = (const float4*)a1; dst = (float4*)o1; off = i - RA_C0; }
    else if (i < RA_C2) { src = (const float4*)a2; dst = (float4*)o2; off = i - RA_C1; }
    else if (i < RA_C3) { src = (const float4*)a3; dst = (float4*)o3; off = i - RA_C2; }
    else if (i < RA_C4) { src = (const float4*)a4; dst = (float4*)o4; off = i - RA_C3; }
    else                { src = (const float4*)a5; dst = (float4*)o5; off = i - RA_C4; }
    float4 v = src[off];
    v.x = to_tf32(v.x); v.y = to_tf32(v.y);
    v.z = to_tf32(v.z); v.w = to_tf32(v.w);
    dst[off] = v;
}

// ---------------- TF32 tensor-core GEMM: C = A(lda) @ B + bias ----------------
#define GBM 128
#define GBN 64
#define GBK 32
#define AS_STRIDE 36
#define BS_STRIDE 72
#define ABUF (GBM * AS_STRIDE)
#define BBUF (GBK * BS_STRIDE)
#define GEMM_SMEM_FLOATS (2 * (ABUF + BBUF))
#define GEMM_SMEM_BYTES  (GEMM_SMEM_FLOATS * 4)

__global__ __launch_bounds__(256, 2)
void gemm_tf32_kernel(const float* __restrict__ A, int lda,
                      const float* __restrict__ B,
                      const float* __restrict__ bias,
                      float* __restrict__ C,
                      int M, int N, int K)
{
    extern __shared__ float sm[];
    int tid  = threadIdx.x;
    int wid  = tid >> 5;
    int lane = tid & 31;
    int wm = wid >> 1;
    int wn = wid & 1;
    int g  = lane >> 2;
    int t  = lane & 3;
    int m0 = blockIdx.y * GBM;
    int n0 = blockIdx.x * GBN;

    float acc[2][4][4];
#pragma unroll
    for (int mi = 0; mi < 2; mi++)
#pragma unroll
        for (int ni = 0; ni < 4; ni++)
#pragma unroll
            for (int j = 0; j < 4; j++) acc[mi][ni][j] = 0.f;

    int nk = K / GBK;

    auto load_tile = [&](int kt, int buf) {
        float* As = sm + buf * (ABUF + BBUF);
        float* Bs = As + ABUF;
        int k0 = kt * GBK;
#pragma unroll
        for (int p = 0; p < 4; p++) {
            int idx = tid + p * 256;
            int r = idx >> 3, c = (idx & 7) * 4;
            cp_async16(&As[r * AS_STRIDE + c],
                       A + (size_t)(m0 + r) * lda + k0 + c);
        }
#pragma unroll
        for (int p = 0; p < 2; p++) {
            int idx = tid + p * 256;
            int r = idx >> 4, c = (idx & 15) * 4;
            cp_async16(&Bs[r * BS_STRIDE + c],
                       B + (size_t)(k0 + r) * N + n0 + c);
        }
        CP_COMMIT();
    };

    load_tile(0, 0);

    for (int kt = 0; kt < nk; kt++) {
        int buf = kt & 1;
        if (kt + 1 < nk) {
            load_tile(kt + 1, buf ^ 1);
            CP_WAIT1();
        } else {
            CP_WAIT0();
        }
        __syncthreads();

        const float* As = sm + buf * (ABUF + BBUF);
        const float* Bs = As + ABUF;

#pragma unroll
        for (int k8 = 0; k8 < 4; k8++) {
            int kc = k8 * 8;
            uint32_t a[2][4];
#pragma unroll
            for (int mi = 0; mi < 2; mi++) {
                int row = wm * 32 + mi * 16;
                a[mi][0] = __float_as_uint(As[(row + g) * AS_STRIDE + kc + t]);
                a[mi][1] = __float_as_uint(As[(row + g + 8) * AS_STRIDE + kc + t]);
                a[mi][2] = __float_as_uint(As[(row + g) * AS_STRIDE + kc + t + 4]);
                a[mi][3] = __float_as_uint(As[(row + g + 8) * AS_STRIDE + kc + t + 4]);
            }
#pragma unroll
            for (int ni = 0; ni < 4; ni++) {
                int col = wn * 32 + ni * 8 + g;
                uint32_t b0 = __float_as_uint(Bs[(kc + t) * BS_STRIDE + col]);
                uint32_t b1 = __float_as_uint(Bs[(kc + t + 4) * BS_STRIDE + col]);
                mma_tf32(acc[0][ni], a[0][0], a[0][1], a[0][2], a[0][3], b0, b1);
                mma_tf32(acc[1][ni], a[1][0], a[1][1], a[1][2], a[1][3], b0, b1);
            }
        }
        __syncthreads();
    }

#pragma unroll
    for (int ni = 0; ni < 4; ni++) {
        int col = n0 + wn * 32 + ni * 8 + 2 * t;
        float2 bv = *(const float2*)(bias + col);
#pragma unroll
        for (int mi = 0; mi < 2; mi++) {
            int r0 = m0 + wm * 32 + mi * 16 + g;
            float2 v0 = make_float2(acc[mi][ni][0] + bv.x, acc[mi][ni][1] + bv.y);
            float2 v1 = make_float2(acc[mi][ni][2] + bv.x, acc[mi][ni][3] + bv.y);
            *(float2*)(C + (size_t)r0 * N + col) = v0;
            *(float2*)(C + (size_t)(r0 + 8) * N + col) = v1;
        }
    }
}

// ---------------- RMSNorm over first 128 cols (stores tf32-rounded) ----------------
__global__ void rmsnorm_kernel(float* __restrict__ data, const float* __restrict__ w,
                               int rows, int stride)
{
    int row = blockIdx.x * 8 + (threadIdx.x >> 5);
    int lane = threadIdx.x & 31;
    if (row >= rows) return;
    float* p = data + (size_t)row * stride;
    float4 v = *(float4*)(p + lane * 4);
    float ss = v.x * v.x + v.y * v.y + v.z * v.z + v.w * v.w;
#pragma unroll
    for (int o = 16; o; o >>= 1) ss += __shfl_xor_sync(0xffffffffu, ss, o);
    float sc = rsqrtf(ss * (1.f / 128.f) + 1e-8f);
    float4 wv = *(const float4*)(w + lane * 4);
    v.x = to_tf32(v.x * wv.x * sc);
    v.y = to_tf32(v.y * wv.y * sc);
    v.z = to_tf32(v.z * wv.z * sc);
    v.w = to_tf32(v.w * wv.w * sc);
    *(float4*)(p + lane * 4) = v;
}

// ---------------- pack Q with RoPE (scaled + tf32-rounded) ----------------
__global__ void pack_q_kernel(const float* __restrict__ q, const int* __restrict__ pos,
                              float* __restrict__ qs)
{
    int idx = blockIdx.x * blockDim.x + threadIdx.x;
    if (idx >= BATCH * NH * S_LEN * QDIM) return;
    int d = idx & 127;
    int s = (idx >> 7) & (S_LEN - 1);
    int h = (idx >> 18) & 7;
    int b = idx >> 21;
    int r = b * S_LEN + s;
    float val;
    if (d < Q_NOPE_) {
        val = q[(size_t)r * 1024 + h * Q_NOPE_ + d];
    } else {
        int j = d - Q_NOPE_;
        int jp = j & ~1;
        int i = jp >> 1;
        const float* base = q + (size_t)r * 1024 + NH * Q_NOPE_ + h * Q_ROPE_;
        float xe = base[jp];
        float xo = base[jp + 1];
        float p = (float)pos[r];
        float inv = powf(10000.f, -(float)(2 * i) / (float)Q_ROPE_);
        float ang = p * inv;
        float sn, cs;
        sincosf(ang, &sn, &cs);
        val = (j & 1) ? (xe * sn + xo * cs) : (xe * cs - xo * sn);
    }
    qs[idx] = to_tf32(val * SM_SCALE);
}

// ---------------- pack K with RoPE (tf32-rounded) ----------------
__global__ void pack_k_kernel(const float* __restrict__ kv, const float* __restrict__ ckvkr,
                              const int* __restrict__ pos, float* __restrict__ ks)
{
    int idx = blockIdx.x * blockDim.x + threadIdx.x;
    if (idx >= BATCH * NH * S_LEN * KDIM) return;
    int d = idx & 127;
    int s = (idx >> 7) & (S_LEN - 1);
    int h = (idx >> 18) & 7;
    int b = idx >> 21;
    int r = b * S_LEN + s;
    float val;
    if (d < K_NOPE_) {
        val = kv[(size_t)r * 2560 + h * K_NOPE_ + d];
    } else {
        int j = d - K_NOPE_;
        int jp = j & ~1;
        int i = jp >> 1;
        const float* base = ckvkr + (size_t)r * 192 + KV_C_;
        float xe = base[jp];
        float xo = base[jp + 1];
        float p = (float)pos[r];
        float inv = powf(10000.f, -(float)(2 * i) / (float)K_ROPE_);
        float ang = p * inv;
        float sn, cs;
        sincosf(ang, &sn, &cs);
        val = (j & 1) ? (xe * sn + xo * cs) : (xe * cs - xo * sn);
    }
    ks[idx] = to_tf32(val);
}

// ---------------- pack V (tf32-rounded) ----------------
__global__ void pack_v_kernel(const float* __restrict__ kv, float* __restrict__ vs)
{
    int idx = blockIdx.x * blockDim.x + threadIdx.x;
    if (idx >= BATCH * NH * S_LEN * V_HD_) return;
    int d = idx & 255;
    int s = (idx >> 8) & (S_LEN - 1);
    int h = (idx >> 19) & 7;
    int b = idx >> 22;
    int r = b * S_LEN + s;
    vs[idx] = to_tf32(kv[(size_t)r * 2560 + NH * K_NOPE_ + h * V_HD_ + d]);
}

// ---------------- TF32 tensor-core flash attention (cp.async pipelined) ----------------
#define QS_STRIDE 132
#define KS_STRIDE 132
#define VS_STRIDE 260
#define PS_STRIDE 68
#define QS_OFF  0
#define KS_OFF  (QS_OFF + 128 * QS_STRIDE)
#define VS_OFF  (KS_OFF + 64 * KS_STRIDE)
#define PS_OFF  (VS_OFF + 64 * VS_STRIDE)
#define STM_OFF (PS_OFF + 128 * PS_STRIDE)
#define STS_OFF (STM_OFF + 256)
#define FLASH_SMEM_FLOATS (STS_OFF + 256)
#define FLASH_SMEM_BYTES  (FLASH_SMEM_FLOATS * 4)
#define NKT (S_LEN / 64)

__global__ __launch_bounds__(512, 1)
void flash_mma_kernel(const float* __restrict__ qs, const float* __restrict__ ks,
                      const float* __restrict__ vs, float* __restrict__ attn)
{
    extern __shared__ float sm[];
    float* Qs  = sm + QS_OFF;
    float* Ks  = sm + KS_OFF;
    float* Vs  = sm + VS_OFF;
    float* Ps  = sm + PS_OFF;
    float* StM = sm + STM_OFF;
    float* StS = sm + STS_OFF;

    int b = blockIdx.z, h = blockIdx.y, qt = blockIdx.x;
    int tid  = threadIdx.x;
    int wid  = tid >> 5;
    int lane = tid & 31;
    int mw = wid >> 1;
    int nw = wid & 1;
    int g  = lane >> 2;
    int t  = lane & 3;

    size_t bh = (size_t)(b * NH + h) * S_LEN;

    // async tile loaders (single-buffered, phase-shifted)
    auto load_k_tile = [&](int kt) {
        const float* Kg = ks + (bh + (size_t)kt * 64) * 128;
#pragma unroll
        for (int p = 0; p < 4; p++) {
            int idx = tid + p * 512;
            int r = idx >> 5, c = (idx & 31) * 4;
            cp_async16(&Ks[r * KS_STRIDE + c], Kg + r * 128 + c);
        }
        CP_COMMIT();
    };
    auto load_v_tile = [&](int kt) {
        const float* Vg = vs + (bh + (size_t)kt * 64) * 256;
#pragma unroll
        for (int p = 0; p < 8; p++) {
            int idx = tid + p * 512;
            int r = idx >> 6, c = (idx & 63) * 4;
            cp_async16(&Vs[r * VS_STRIDE + c], Vg + r * 256 + c);
        }
        CP_COMMIT();
    };

    // prefetch K[0], then load Q while it streams
    load_k_tile(0);
    {
        const float4* Qg = (const float4*)(qs + (bh + (size_t)qt * 128) * 128);
#pragma unroll
        for (int p = 0; p < 8; p++) {
            int r = wid + p * 16;
            *(float4*)&Qs[r * QS_STRIDE + lane * 4] = Qg[r * 32 + lane];
        }
    }

    int qrow = mw * 16;
    float m0 = -1e30f, m1 = -1e30f, l0 = 0.f, l1 = 0.f;
    float o[16][4];
#pragma unroll
    for (int dt = 0; dt < 16; dt++)
#pragma unroll
        for (int j = 0; j < 4; j++) o[dt][j] = 0.f;

    for (int kt = 0; kt < NKT; kt++) {
        CP_WAIT0();            // K[kt] resident; also guarantees V[kt-1] drained
        __syncthreads();       // all threads past previous PV -> V buffer free

        load_v_tile(kt);       // streams during QK + softmax

        // ---- scores: warp computes 16 rows x 32 key-cols ----
        float c[4][4];
#pragma unroll
        for (int nt = 0; nt < 4; nt++)
#pragma unroll
            for (int j = 0; j < 4; j++) c[nt][j] = 0.f;

#pragma unroll
        for (int k8 = 0; k8 < 16; k8++) {
            int kc = k8 * 8;
            uint32_t a0 = __float_as_uint(Qs[(qrow + g) * QS_STRIDE + kc + t]);
            uint32_t a1 = __float_as_uint(Qs[(qrow + g + 8) * QS_STRIDE + kc + t]);
            uint32_t a2 = __float_as_uint(Qs[(qrow + g) * QS_STRIDE + kc + t + 4]);
            uint32_t a3 = __float_as_uint(Qs[(qrow + g + 8) * QS_STRIDE + kc + t + 4]);
#pragma unroll
            for (int nt = 0; nt < 4; nt++) {
                int ncol = nw * 32 + nt * 8 + g;
                uint32_t b0 = __float_as_uint(Ks[ncol * KS_STRIDE + kc + t]);
                uint32_t b1 = __float_as_uint(Ks[ncol * KS_STRIDE + kc + t + 4]);
                mma_tf32(c[nt], a0, a1, a2, a3, b0, b1);
            }
        }

        // ---- online softmax partials ----
        float pm0 = -1e30f, pm1 = -1e30f;
#pragma unroll
        for (int nt = 0; nt < 4; nt++) {
            pm0 = fmaxf(pm0, fmaxf(c[nt][0], c[nt][1]));
            pm1 = fmaxf(pm1, fmaxf(c[nt][2], c[nt][3]));
        }
        pm0 = fmaxf(pm0, __shfl_xor_sync(0xffffffffu, pm0, 1));
        pm0 = fmaxf(pm0, __shfl_xor_sync(0xffffffffu, pm0, 2));
        pm1 = fmaxf(pm1, __shfl_xor_sync(0xffffffffu, pm1, 1));
        pm1 = fmaxf(pm1, __shfl_xor_sync(0xffffffffu, pm1, 2));

        float ex[4][4];
        float ps0 = 0.f, ps1 = 0.f;
#pragma unroll
        for (int nt = 0; nt < 4; nt++) {
            ex[nt][0] = __expf(c[nt][0] - pm0);
            ex[nt][1] = __expf(c[nt][1] - pm0);
            ex[nt][2] = __expf(c[nt][2] - pm1);
            ex[nt][3] = __expf(c[nt][3] - pm1);
            ps0 += ex[nt][0] + ex[nt][1];
            ps1 += ex[nt][2] + ex[nt][3];
        }
        ps0 += __shfl_xor_sync(0xffffffffu, ps0, 1);
        ps0 += __shfl_xor_sync(0xffffffffu, ps0, 2);
        ps1 += __shfl_xor_sync(0xffffffffu, ps1, 1);
        ps1 += __shfl_xor_sync(0xffffffffu, ps1, 2);

        if (t == 0) {
            StM[nw * 128 + qrow + g]     = pm0;
            StM[nw * 128 + qrow + g + 8] = pm1;
            StS[nw * 128 + qrow + g]     = ps0;
            StS[nw * 128 + qrow + g + 8] = ps1;
        }
        __syncthreads();       // also: all threads past QK -> K buffer free

        // prefetch K[kt+1] while softmax combine + P-write + PV run
        if (kt + 1 < NKT) load_k_tile(kt + 1);

        int ow = 1 - nw;
        float pmO0 = StM[ow * 128 + qrow + g];
        float pmO1 = StM[ow * 128 + qrow + g + 8];
        float psO0 = StS[ow * 128 + qrow + g];
        float psO1 = StS[ow * 128 + qrow + g + 8];

        float mn0 = fmaxf(pm0, pmO0);
        float mn1 = fmaxf(pm1, pmO1);
        float rs0 = ps0 * __expf(pm0 - mn0) + psO0 * __expf(pmO0 - mn0);
        float rs1 = ps1 * __expf(pm1 - mn1) + psO1 * __expf(pmO1 - mn1);

        float mnew0 = fmaxf(m0, mn0);
        float mnew1 = fmaxf(m1, mn1);
        float corr0 = __expf(m0 - mnew0);
        float corr1 = __expf(m1 - mnew1);
        l0 = l0 * corr0 + rs0 * __expf(mn0 - mnew0);
        l1 = l1 * corr1 + rs1 * __expf(mn1 - mnew1);
        m0 = mnew0;
        m1 = mnew1;

#pragma unroll
        for (int dt = 0; dt < 16; dt++) {
            o[dt][0] *= corr0;
            o[dt][1] *= corr0;
            o[dt][2] *= corr1;
            o[dt][3] *= corr1;
        }

        float f0 = __expf(pm0 - mnew0);
        float f1 = __expf(pm1 - mnew1);
#pragma unroll
        for (int nt = 0; nt < 4; nt++) {
            int col = nw * 32 + nt * 8 + 2 * t;
            Ps[(qrow + g) * PS_STRIDE + col]         = to_tf32(ex[nt][0] * f0);
            Ps[(qrow + g) * PS_STRIDE + col + 1]     = to_tf32(ex[nt][1] * f0);
            Ps[(qrow + g + 8) * PS_STRIDE + col]     = to_tf32(ex[nt][2] * f1);
            Ps[(qrow + g + 8) * PS_STRIDE + col + 1] = to_tf32(ex[nt][3] * f1);
        }

        // V[kt] must be resident (leave K[kt+1] group in flight)
        if (kt + 1 < NKT) { CP_WAIT1(); } else { CP_WAIT0(); }
        __syncthreads();       // P visible + V resident

        // ---- O += P @ V (overlaps K[kt+1] stream) ----
#pragma unroll
        for (int k8 = 0; k8 < 8; k8++) {
            int kc = k8 * 8;
            uint32_t a0 = __float_as_uint(Ps[(qrow + g) * PS_STRIDE + kc + t]);
            uint32_t a1 = __float_as_uint(Ps[(qrow + g + 8) * PS_STRIDE + kc + t]);
            uint32_t a2 = __float_as_uint(Ps[(qrow + g) * PS_STRIDE + kc + t + 4]);
            uint32_t a3 = __float_as_uint(Ps[(qrow + g + 8) * PS_STRIDE + kc + t + 4]);
#pragma unroll
            for (int dt = 0; dt < 16; dt++) {
                int dv = nw * 128 + dt * 8 + g;
                uint32_t b0 = __float_as_uint(Vs[(kc + t) * VS_STRIDE + dv]);
                uint32_t b1 = __float_as_uint(Vs[(kc + t + 4) * VS_STRIDE + dv]);
                mma_tf32(o[dt], a0, a1, a2, a3, b0, b1);
            }
        }
    }

    // epilogue: normalize, round to tf32 (feeds the w_o tf32 GEMM), write
    float inv0 = 1.f / l0;
    float inv1 = 1.f / l1;
    int row0 = b * S_LEN + qt * 128 + qrow + g;
    int row1 = row0 + 8;
#pragma unroll
    for (int dt = 0; dt < 16; dt++) {
        int col = h * V_HD_ + nw * 128 + dt * 8 + 2 * t;
        float2 v0 = make_float2(to_tf32(o[dt][0] * inv0), to_tf32(o[dt][1] * inv0));
        float2 v1 = make_float2(to_tf32(o[dt][2] * inv1), to_tf32(o[dt][3] * inv1));
        *(float2*)(attn + (size_t)row0 * (NH * V_HD_) + col) = v0;
        *(float2*)(attn + (size_t)row1 * (NH * V_HD_) + col) = v1;
    }
}

// ---------------- host launcher ----------------
extern "C" void kernel_launch(void* const* d_in, const int* in_sizes, int n_in,
                              void* d_out, int out_size)
{
    const float* x         = (const float*)d_in[0];
    const int*   pos       = (const int*)  d_in[1];
    const float* w_dq_w    = (const float*)d_in[2];
    const float* w_dq_b    = (const float*)d_in[3];
    const float* q_norm_w  = (const float*)d_in[4];
    const float* w_uq_qr_w = (const float*)d_in[5];
    const float* w_uq_qr_b = (const float*)d_in[6];
    const float* w_dkv_kr_w= (const float*)d_in[7];
    const float* w_dkv_kr_b= (const float*)d_in[8];
    const float* kv_norm_w = (const float*)d_in[9];
    const float* w_uk_uv_w = (const float*)d_in[10];
    const float* w_uk_uv_b = (const float*)d_in[11];
    const float* w_o_w     = (const float*)d_in[12];
    const float* w_o_b     = (const float*)d_in[13];
    float* out = (float*)d_out;

    float *cq, *ckvkr, *q, *kv, *qsb, *ksb, *vsb, *attn;
    float *x32, *w1, *w2, *w3, *w4, *w5;
    cudaGetSymbolAddress((void**)&cq,    g_cq);
    cudaGetSymbolAddress((void**)&ckvkr, g_ckvkr);
    cudaGetSymbolAddress((void**)&q,     g_q);
    cudaGetSymbolAddress((void**)&kv,    g_kv);
    cudaGetSymbolAddress((void**)&qsb,   g_qs);
    cudaGetSymbolAddress((void**)&ksb,   g_ks);
    cudaGetSymbolAddress((void**)&vsb,   g_vs);
    cudaGetSymbolAddress((void**)&attn,  g_attn);
    cudaGetSymbolAddress((void**)&x32,   g_x32);
    cudaGetSymbolAddress((void**)&w1,    g_w1);
    cudaGetSymbolAddress((void**)&w2,    g_w2);
    cudaGetSymbolAddress((void**)&w3,    g_w3);
    cudaGetSymbolAddress((void**)&w4,    g_w4);
    cudaGetSymbolAddress((void**)&w5,    g_w5);

    cudaFuncSetAttribute(flash_mma_kernel, cudaFuncAttributeMaxDynamicSharedMemorySize,
                         FLASH_SMEM_BYTES);
    cudaFuncSetAttribute(gemm_tf32_kernel, cudaFuncAttributeMaxDynamicSharedMemorySize,
                         GEMM_SMEM_BYTES);

    // one fused tf32 rounding pass over x + all 5 weights
    round_all_kernel<<<RA_C5 / 256, 256>>>(x, x32, w_dq_w, w1, w_uq_qr_w, w2,
                                           w_dkv_kr_w, w3, w_uk_uv_w, w4, w_o_w, w5);

    dim3 blk(256);

    gemm_tf32_kernel<<<dim3(128 / GBN, NROWS / GBM), blk, GEMM_SMEM_BYTES>>>(
        x32, DIM_, w1, w_dq_b, cq, NROWS, 128, DIM_);
    rmsnorm_kernel<<<NROWS / 8, 256>>>(cq, q_norm_w, NROWS, 128);

    gemm_tf32_kernel<<<dim3(192 / GBN, NROWS / GBM), blk, GEMM_SMEM_BYTES>>>(
        x32, DIM_, w3, w_dkv_kr_b, ckvkr, NROWS, 192, DIM_);
    rmsnorm_kernel<<<NROWS / 8, 256>>>(ckvkr, kv_norm_w, NROWS, 192);

    gemm_tf32_kernel<<<dim3(1024 / GBN, NROWS / GBM), blk, GEMM_SMEM_BYTES>>>(
        cq, 128, w2, w_uq_qr_b, q, NROWS, 1024, 128);

    gemm_tf32_kernel<<<dim3(2560 / GBN, NROWS / GBM), blk, GEMM_SMEM_BYTES>>>(
        ckvkr, 192, w4, w_uk_uv_b, kv, NROWS, 2560, 128);

    pack_q_kernel<<<(BATCH * NH * S_LEN * QDIM) / 256, 256>>>(q, pos, qsb);
    pack_k_kernel<<<(BATCH * NH * S_LEN * KDIM) / 256, 256>>>(kv, ckvkr, pos, ksb);
    pack_v_kernel<<<(BATCH * NH * S_LEN * V_HD_) / 256, 256>>>(kv, vsb);

    flash_mma_kernel<<<dim3(S_LEN / 128, NH, BATCH), 512, FLASH_SMEM_BYTES>>>(qsb, ksb, vsb, attn);

    gemm_tf32_kernel<<<dim3(1024 / GBN, NROWS / GBM), blk, GEMM_SMEM_BYTES>>>(
        attn, NH * V_HD_, w5, w_o_b, out, NROWS, 1024, 2048);
}

// round 6
// speedup vs baseline: 4.2247x; 1.0707x over previous
#include <cuda_runtime.h>
#include <math.h>
#include <stdint.h>

// ---------------- problem constants ----------------
#define BATCH   2
#define S_LEN   2048
#define NROWS   (BATCH * S_LEN)     // 4096
#define DIM_    1024
#define NH      8
#define Q_C_    128
#define Q_NOPE_ 96
#define Q_ROPE_ 32
#define KV_C_   128
#define K_NOPE_ 64
#define K_ROPE_ 64
#define V_HD_   256
#define QDIM    128
#define KDIM    128
#define SM_SCALE 0.08838834764831845f   // 1/sqrt(128)
#define CQKV_N  384                      // 128 (cq) + 192 (ckv_kr) + 64 pad

// ---------------- scratch (static device arrays; no allocations) ----------------
__device__ float g_cqkv [(size_t)NROWS * CQKV_N];   // fused cq|ckv_kr|pad
__device__ float g_q    [(size_t)NROWS * 1024];
__device__ float g_kv   [(size_t)NROWS * 2560];
__device__ float g_qs   [(size_t)BATCH * NH * S_LEN * QDIM];
__device__ float g_ks   [(size_t)BATCH * NH * S_LEN * KDIM];
__device__ float g_vs   [(size_t)BATCH * NH * S_LEN * V_HD_];
__device__ float g_attn [(size_t)NROWS * (NH * V_HD_)];
// tf32-rounded operands
__device__ float g_x32  [(size_t)NROWS * DIM_];
__device__ float g_w13  [(size_t)DIM_ * CQKV_N];    // packed w_dq | w_dkv_kr | 0
__device__ float g_b13  [CQKV_N];
__device__ float g_w2   [(size_t)Q_C_ * 1024];
__device__ float g_w4   [(size_t)KV_C_ * 2560];
__device__ float g_w5   [(size_t)2048 * DIM_];

// ---------------- helpers ----------------
__device__ __forceinline__ float to_tf32(float x) {
    uint32_t u;
    asm("cvt.rna.tf32.f32 %0, %1;" : "=r"(u) : "f"(x));
    return __uint_as_float(u);
}

__device__ __forceinline__ void mma_tf32(float* c, uint32_t a0, uint32_t a1,
                                         uint32_t a2, uint32_t a3,
                                         uint32_t b0, uint32_t b1) {
    asm volatile(
        "mma.sync.aligned.m16n8k8.row.col.f32.tf32.tf32.f32 "
        "{%0,%1,%2,%3}, {%4,%5,%6,%7}, {%8,%9}, {%0,%1,%2,%3};"
        : "+f"(c[0]), "+f"(c[1]), "+f"(c[2]), "+f"(c[3])
        : "r"(a0), "r"(a1), "r"(a2), "r"(a3), "r"(b0), "r"(b1));
}

__device__ __forceinline__ void cp_async16(void* smem_ptr, const void* gptr) {
    uint32_t s = (uint32_t)__cvta_generic_to_shared(smem_ptr);
    asm volatile("cp.async.cg.shared.global [%0], [%1], 16;" :: "r"(s), "l"(gptr));
}
#define CP_COMMIT() asm volatile("cp.async.commit_group;")
#define CP_WAIT0()  asm volatile("cp.async.wait_group 0;")
#define CP_WAIT1()  asm volatile("cp.async.wait_group 1;")

// ---------------- fused tf32 rounding / weight packing pass ----------------
// ranges (in float4 units)
#define RA_X   1048576                         // x
#define RA_W2  (RA_X  + 32768)                 // w2
#define RA_W4  (RA_W2 + 81920)                 // w4
#define RA_W5  (RA_W4 + 524288)                // w5
#define RA_W13 (RA_W5 + 98304)                 // packed w13 (1024*384/4)
#define RA_B13 (RA_W13 + 96)                   // packed b13 (384/4)
#define RA_TOTAL RA_B13

__global__ __launch_bounds__(256)
void round_all_kernel(const float* __restrict__ x,    float* __restrict__ ox,
                      const float* __restrict__ w2i,  float* __restrict__ w2o,
                      const float* __restrict__ w4i,  float* __restrict__ w4o,
                      const float* __restrict__ w5i,  float* __restrict__ w5o,
                      const float* __restrict__ w1i,  const float* __restrict__ w3i,
                      float* __restrict__ w13o,
                      const float* __restrict__ b1i,  const float* __restrict__ b3i,
                      float* __restrict__ b13o)
{
    int i = blockIdx.x * 256 + threadIdx.x;
    if (i >= RA_TOTAL) return;
    float4 v;
    float4* dst;
    if (i < RA_X)       { v = ((const float4*)x)[i];             dst = (float4*)ox  + i; }
    else if (i < RA_W2) { int o = i - RA_X;  v = ((const float4*)w2i)[o]; dst = (float4*)w2o + o; }
    else if (i < RA_W4) { int o = i - RA_W2; v = ((const float4*)w4i)[o]; dst = (float4*)w4o + o; }
    else if (i < RA_W5) { int o = i - RA_W4; v = ((const float4*)w5i)[o]; dst = (float4*)w5o + o; }
    else if (i < RA_W13) {
        int o = i - RA_W5;
        int k = o / 96, c4 = (o % 96) * 4;
        if (c4 < 128)      v = *(const float4*)(w1i + (size_t)k * 128 + c4);
        else if (c4 < 320) v = *(const float4*)(w3i + (size_t)k * 192 + (c4 - 128));
        else               v = make_float4(0.f, 0.f, 0.f, 0.f);
        dst = (float4*)w13o + o;
    } else {
        int o = i - RA_W13;
        int c4 = o * 4;
        if (c4 < 128)      v = *(const float4*)(b1i + c4);
        else if (c4 < 320) v = *(const float4*)(b3i + (c4 - 128));
        else               v = make_float4(0.f, 0.f, 0.f, 0.f);
        *(float4*)(b13o + c4) = v;   // bias used in fp32, no rounding needed
        return;
    }
    v.x = to_tf32(v.x); v.y = to_tf32(v.y);
    v.z = to_tf32(v.z); v.w = to_tf32(v.w);
    *dst = v;
}

// ---------------- TF32 tensor-core GEMM: C = A(lda) @ B + bias ----------------
// CTA 128x128, BK=32, 256 threads, 8 warps = 4(M) x 2(N), warp tile 32x64.
#define GBM 128
#define GBN 128
#define GBK 32
#define AS_STRIDE 36
#define BS_STRIDE 136
#define ABUF (GBM * AS_STRIDE)                 // 4608 floats
#define BBUF (GBK * BS_STRIDE)                 // 4352 floats
#define GEMM_SMEM_FLOATS (2 * (ABUF + BBUF))   // 17920
#define GEMM_SMEM_BYTES  (GEMM_SMEM_FLOATS * 4)

__global__ __launch_bounds__(256, 2)
void gemm_tf32_kernel(const float* __restrict__ A, int lda,
                      const float* __restrict__ B,
                      const float* __restrict__ bias,
                      float* __restrict__ C,
                      int M, int N, int K)
{
    extern __shared__ float sm[];
    int tid  = threadIdx.x;
    int wid  = tid >> 5;
    int lane = tid & 31;
    int wm = wid >> 1;          // 0..3  (32-row slice)
    int wn = wid & 1;           // 0..1  (64-col slice)
    int g  = lane >> 2;
    int t  = lane & 3;
    int m0 = blockIdx.y * GBM;
    int n0 = blockIdx.x * GBN;

    float acc[2][8][4];
#pragma unroll
    for (int mi = 0; mi < 2; mi++)
#pragma unroll
        for (int ni = 0; ni < 8; ni++)
#pragma unroll
            for (int j = 0; j < 4; j++) acc[mi][ni][j] = 0.f;

    int nk = K / GBK;

    auto load_tile = [&](int kt, int buf) {
        float* As = sm + buf * (ABUF + BBUF);
        float* Bs = As + ABUF;
        int k0 = kt * GBK;
#pragma unroll
        for (int p = 0; p < 4; p++) {           // A: 128x32 = 1024 float4
            int idx = tid + p * 256;
            int r = idx >> 3, c = (idx & 7) * 4;
            cp_async16(&As[r * AS_STRIDE + c],
                       A + (size_t)(m0 + r) * lda + k0 + c);
        }
#pragma unroll
        for (int p = 0; p < 4; p++) {           // B: 32x128 = 1024 float4
            int idx = tid + p * 256;
            int r = idx >> 5, c = (idx & 31) * 4;
            cp_async16(&Bs[r * BS_STRIDE + c],
                       B + (size_t)(k0 + r) * N + n0 + c);
        }
        CP_COMMIT();
    };

    load_tile(0, 0);

    for (int kt = 0; kt < nk; kt++) {
        int buf = kt & 1;
        if (kt + 1 < nk) {
            load_tile(kt + 1, buf ^ 1);
            CP_WAIT1();
        } else {
            CP_WAIT0();
        }
        __syncthreads();

        const float* As = sm + buf * (ABUF + BBUF);
        const float* Bs = As + ABUF;

#pragma unroll
        for (int k8 = 0; k8 < 4; k8++) {
            int kc = k8 * 8;
            uint32_t a[2][4];
#pragma unroll
            for (int mi = 0; mi < 2; mi++) {
                int row = wm * 32 + mi * 16;
                a[mi][0] = __float_as_uint(As[(row + g) * AS_STRIDE + kc + t]);
                a[mi][1] = __float_as_uint(As[(row + g + 8) * AS_STRIDE + kc + t]);
                a[mi][2] = __float_as_uint(As[(row + g) * AS_STRIDE + kc + t + 4]);
                a[mi][3] = __float_as_uint(As[(row + g + 8) * AS_STRIDE + kc + t + 4]);
            }
#pragma unroll
            for (int ni = 0; ni < 8; ni++) {
                int col = wn * 64 + ni * 8 + g;
                uint32_t b0 = __float_as_uint(Bs[(kc + t) * BS_STRIDE + col]);
                uint32_t b1 = __float_as_uint(Bs[(kc + t + 4) * BS_STRIDE + col]);
                mma_tf32(acc[0][ni], a[0][0], a[0][1], a[0][2], a[0][3], b0, b1);
                mma_tf32(acc[1][ni], a[1][0], a[1][1], a[1][2], a[1][3], b0, b1);
            }
        }
        __syncthreads();
    }

#pragma unroll
    for (int ni = 0; ni < 8; ni++) {
        int col = n0 + wn * 64 + ni * 8 + 2 * t;
        float2 bv = *(const float2*)(bias + col);
#pragma unroll
        for (int mi = 0; mi < 2; mi++) {
            int r0 = m0 + wm * 32 + mi * 16 + g;
            float2 v0 = make_float2(acc[mi][ni][0] + bv.x, acc[mi][ni][1] + bv.y);
            float2 v1 = make_float2(acc[mi][ni][2] + bv.x, acc[mi][ni][3] + bv.y);
            *(float2*)(C + (size_t)r0 * N + col) = v0;
            *(float2*)(C + (size_t)(r0 + 8) * N + col) = v1;
        }
    }
}

// ---------------- RMSNorm over 128 cols at given base/stride (tf32 out) ----------------
__global__ void rmsnorm_kernel(float* __restrict__ data, const float* __restrict__ w,
                               int rows, int stride)
{
    int row = blockIdx.x * 8 + (threadIdx.x >> 5);
    int lane = threadIdx.x & 31;
    if (row >= rows) return;
    float* p = data + (size_t)row * stride;
    float4 v = *(float4*)(p + lane * 4);
    float ss = v.x * v.x + v.y * v.y + v.z * v.z + v.w * v.w;
#pragma unroll
    for (int o = 16; o; o >>= 1) ss += __shfl_xor_sync(0xffffffffu, ss, o);
    float sc = rsqrtf(ss * (1.f / 128.f) + 1e-8f);
    float4 wv = *(const float4*)(w + lane * 4);
    v.x = to_tf32(v.x * wv.x * sc);
    v.y = to_tf32(v.y * wv.y * sc);
    v.z = to_tf32(v.z * wv.z * sc);
    v.w = to_tf32(v.w * wv.w * sc);
    *(float4*)(p + lane * 4) = v;
}

// ---------------- pack Q with RoPE (scaled + tf32-rounded) ----------------
__global__ void pack_q_kernel(const float* __restrict__ q, const int* __restrict__ pos,
                              float* __restrict__ qs)
{
    int idx = blockIdx.x * blockDim.x + threadIdx.x;
    if (idx >= BATCH * NH * S_LEN * QDIM) return;
    int d = idx & 127;
    int s = (idx >> 7) & (S_LEN - 1);
    int h = (idx >> 18) & 7;
    int b = idx >> 21;
    int r = b * S_LEN + s;
    float val;
    if (d < Q_NOPE_) {
        val = q[(size_t)r * 1024 + h * Q_NOPE_ + d];
    } else {
        int j = d - Q_NOPE_;
        int jp = j & ~1;
        int i = jp >> 1;
        const float* base = q + (size_t)r * 1024 + NH * Q_NOPE_ + h * Q_ROPE_;
        float xe = base[jp];
        float xo = base[jp + 1];
        float p = (float)pos[r];
        float inv = powf(10000.f, -(float)(2 * i) / (float)Q_ROPE_);
        float ang = p * inv;
        float sn, cs;
        sincosf(ang, &sn, &cs);
        val = (j & 1) ? (xe * sn + xo * cs) : (xe * cs - xo * sn);
    }
    qs[idx] = to_tf32(val * SM_SCALE);
}

// ---------------- pack K with RoPE (tf32-rounded) ----------------
// k_rope source now lives at col 256 of the fused cqkv buffer (stride 384)
__global__ void pack_k_kernel(const float* __restrict__ kv, const float* __restrict__ cqkv,
                              const int* __restrict__ pos, float* __restrict__ ks)
{
    int idx = blockIdx.x * blockDim.x + threadIdx.x;
    if (idx >= BATCH * NH * S_LEN * KDIM) return;
    int d = idx & 127;
    int s = (idx >> 7) & (S_LEN - 1);
    int h = (idx >> 18) & 7;
    int b = idx >> 21;
    int r = b * S_LEN + s;
    float val;
    if (d < K_NOPE_) {
        val = kv[(size_t)r * 2560 + h * K_NOPE_ + d];
    } else {
        int j = d - K_NOPE_;
        int jp = j & ~1;
        int i = jp >> 1;
        const float* base = cqkv + (size_t)r * CQKV_N + 256;
        float xe = base[jp];
        float xo = base[jp + 1];
        float p = (float)pos[r];
        float inv = powf(10000.f, -(float)(2 * i) / (float)K_ROPE_);
        float ang = p * inv;
        float sn, cs;
        sincosf(ang, &sn, &cs);
        val = (j & 1) ? (xe * sn + xo * cs) : (xe * cs - xo * sn);
    }
    ks[idx] = to_tf32(val);
}

// ---------------- pack V (tf32-rounded) ----------------
__global__ void pack_v_kernel(const float* __restrict__ kv, float* __restrict__ vs)
{
    int idx = blockIdx.x * blockDim.x + threadIdx.x;
    if (idx >= BATCH * NH * S_LEN * V_HD_) return;
    int d = idx & 255;
    int s = (idx >> 8) & (S_LEN - 1);
    int h = (idx >> 19) & 7;
    int b = idx >> 22;
    int r = b * S_LEN + s;
    vs[idx] = to_tf32(kv[(size_t)r * 2560 + NH * K_NOPE_ + h * V_HD_ + d]);
}

// ---------------- TF32 tensor-core flash attention (cp.async pipelined) ----------------
#define QS_STRIDE 132
#define KS_STRIDE 132
#define VS_STRIDE 260
#define PS_STRIDE 68
#define QS_OFF  0
#define KS_OFF  (QS_OFF + 128 * QS_STRIDE)
#define VS_OFF  (KS_OFF + 64 * KS_STRIDE)
#define PS_OFF  (VS_OFF + 64 * VS_STRIDE)
#define STM_OFF (PS_OFF + 128 * PS_STRIDE)
#define STS_OFF (STM_OFF + 256)
#define FLASH_SMEM_FLOATS (STS_OFF + 256)
#define FLASH_SMEM_BYTES  (FLASH_SMEM_FLOATS * 4)
#define NKT (S_LEN / 64)

__global__ __launch_bounds__(512, 1)
void flash_mma_kernel(const float* __restrict__ qs, const float* __restrict__ ks,
                      const float* __restrict__ vs, float* __restrict__ attn)
{
    extern __shared__ float sm[];
    float* Qs  = sm + QS_OFF;
    float* Ks  = sm + KS_OFF;
    float* Vs  = sm + VS_OFF;
    float* Ps  = sm + PS_OFF;
    float* StM = sm + STM_OFF;
    float* StS = sm + STS_OFF;

    int b = blockIdx.z, h = blockIdx.y, qt = blockIdx.x;
    int tid  = threadIdx.x;
    int wid  = tid >> 5;
    int lane = tid & 31;
    int mw = wid >> 1;
    int nw = wid & 1;
    int g  = lane >> 2;
    int t  = lane & 3;

    size_t bh = (size_t)(b * NH + h) * S_LEN;

    auto load_k_tile = [&](int kt) {
        const float* Kg = ks + (bh + (size_t)kt * 64) * 128;
#pragma unroll
        for (int p = 0; p < 4; p++) {
            int idx = tid + p * 512;
            int r = idx >> 5, c = (idx & 31) * 4;
            cp_async16(&Ks[r * KS_STRIDE + c], Kg + r * 128 + c);
        }
        CP_COMMIT();
    };
    auto load_v_tile = [&](int kt) {
        const float* Vg = vs + (bh + (size_t)kt * 64) * 256;
#pragma unroll
        for (int p = 0; p < 8; p++) {
            int idx = tid + p * 512;
            int r = idx >> 6, c = (idx & 63) * 4;
            cp_async16(&Vs[r * VS_STRIDE + c], Vg + r * 256 + c);
        }
        CP_COMMIT();
    };

    load_k_tile(0);
    {
        const float4* Qg = (const float4*)(qs + (bh + (size_t)qt * 128) * 128);
#pragma unroll
        for (int p = 0; p < 8; p++) {
            int r = wid + p * 16;
            *(float4*)&Qs[r * QS_STRIDE + lane * 4] = Qg[r * 32 + lane];
        }
    }

    int qrow = mw * 16;
    float m0 = -1e30f, m1 = -1e30f, l0 = 0.f, l1 = 0.f;
    float o[16][4];
#pragma unroll
    for (int dt = 0; dt < 16; dt++)
#pragma unroll
        for (int j = 0; j < 4; j++) o[dt][j] = 0.f;

    for (int kt = 0; kt < NKT; kt++) {
        CP_WAIT0();
        __syncthreads();

        load_v_tile(kt);

        float c[4][4];
#pragma unroll
        for (int nt = 0; nt < 4; nt++)
#pragma unroll
            for (int j = 0; j < 4; j++) c[nt][j] = 0.f;

#pragma unroll
        for (int k8 = 0; k8 < 16; k8++) {
            int kc = k8 * 8;
            uint32_t a0 = __float_as_uint(Qs[(qrow + g) * QS_STRIDE + kc + t]);
            uint32_t a1 = __float_as_uint(Qs[(qrow + g + 8) * QS_STRIDE + kc + t]);
            uint32_t a2 = __float_as_uint(Qs[(qrow + g) * QS_STRIDE + kc + t + 4]);
            uint32_t a3 = __float_as_uint(Qs[(qrow + g + 8) * QS_STRIDE + kc + t + 4]);
#pragma unroll
            for (int nt = 0; nt < 4; nt++) {
                int ncol = nw * 32 + nt * 8 + g;
                uint32_t b0 = __float_as_uint(Ks[ncol * KS_STRIDE + kc + t]);
                uint32_t b1 = __float_as_uint(Ks[ncol * KS_STRIDE + kc + t + 4]);
                mma_tf32(c[nt], a0, a1, a2, a3, b0, b1);
            }
        }

        float pm0 = -1e30f, pm1 = -1e30f;
#pragma unroll
        for (int nt = 0; nt < 4; nt++) {
            pm0 = fmaxf(pm0, fmaxf(c[nt][0], c[nt][1]));
            pm1 = fmaxf(pm1, fmaxf(c[nt][2], c[nt][3]));
        }
        pm0 = fmaxf(pm0, __shfl_xor_sync(0xffffffffu, pm0, 1));
        pm0 = fmaxf(pm0, __shfl_xor_sync(0xffffffffu, pm0, 2));
        pm1 = fmaxf(pm1, __shfl_xor_sync(0xffffffffu, pm1, 1));
        pm1 = fmaxf(pm1, __shfl_xor_sync(0xffffffffu, pm1, 2));

        float ex[4][4];
        float ps0 = 0.f, ps1 = 0.f;
#pragma unroll
        for (int nt = 0; nt < 4; nt++) {
            ex[nt][0] = __expf(c[nt][0] - pm0);
            ex[nt][1] = __expf(c[nt][1] - pm0);
            ex[nt][2] = __expf(c[nt][2] - pm1);
            ex[nt][3] = __expf(c[nt][3] - pm1);
            ps0 += ex[nt][0] + ex[nt][1];
            ps1 += ex[nt][2] + ex[nt][3];
        }
        ps0 += __shfl_xor_sync(0xffffffffu, ps0, 1);
        ps0 += __shfl_xor_sync(0xffffffffu, ps0, 2);
        ps1 += __shfl_xor_sync(0xffffffffu, ps1, 1);
        ps1 += __shfl_xor_sync(0xffffffffu, ps1, 2);

        if (t == 0) {
            StM[nw * 128 + qrow + g]     = pm0;
            StM[nw * 128 + qrow + g + 8] = pm1;
            StS[nw * 128 + qrow + g]     = ps0;
            StS[nw * 128 + qrow + g + 8] = ps1;
        }
        __syncthreads();

        if (kt + 1 < NKT) load_k_tile(kt + 1);

        int ow = 1 - nw;
        float pmO0 = StM[ow * 128 + qrow + g];
        float pmO1 = StM[ow * 128 + qrow + g + 8];
        float psO0 = StS[ow * 128 + qrow + g];
        float psO1 = StS[ow * 128 + qrow + g + 8];

        float mn0 = fmaxf(pm0, pmO0);
        float mn1 = fmaxf(pm1, pmO1);
        float rs0 = ps0 * __expf(pm0 - mn0) + psO0 * __expf(pmO0 - mn0);
        float rs1 = ps1 * __expf(pm1 - mn1) + psO1 * __expf(pmO1 - mn1);

        float mnew0 = fmaxf(m0, mn0);
        float mnew1 = fmaxf(m1, mn1);
        float corr0 = __expf(m0 - mnew0);
        float corr1 = __expf(m1 - mnew1);
        l0 = l0 * corr0 + rs0 * __expf(mn0 - mnew0);
        l1 = l1 * corr1 + rs1 * __expf(mn1 - mnew1);
        m0 = mnew0;
        m1 = mnew1;

#pragma unroll
        for (int dt = 0; dt < 16; dt++) {
            o[dt][0] *= corr0;
            o[dt][1] *= corr0;
            o[dt][2] *= corr1;
            o[dt][3] *= corr1;
        }

        float f0 = __expf(pm0 - mnew0);
        float f1 = __expf(pm1 - mnew1);
#pragma unroll
        for (int nt = 0; nt < 4; nt++) {
            int col = nw * 32 + nt * 8 + 2 * t;
            Ps[(qrow + g) * PS_STRIDE + col]         = to_tf32(ex[nt][0] * f0);
            Ps[(qrow + g) * PS_STRIDE + col + 1]     = to_tf32(ex[nt][1] * f0);
            Ps[(qrow + g + 8) * PS_STRIDE + col]     = to_tf32(ex[nt][2] * f1);
            Ps[(qrow + g + 8) * PS_STRIDE + col + 1] = to_tf32(ex[nt][3] * f1);
        }

        if (kt + 1 < NKT) { CP_WAIT1(); } else { CP_WAIT0(); }
        __syncthreads();

#pragma unroll
        for (int k8 = 0; k8 < 8; k8++) {
            int kc = k8 * 8;
            uint32_t a0 = __float_as_uint(Ps[(qrow + g) * PS_STRIDE + kc + t]);
            uint32_t a1 = __float_as_uint(Ps[(qrow + g + 8) * PS_STRIDE + kc + t]);
            uint32_t a2 = __float_as_uint(Ps[(qrow + g) * PS_STRIDE + kc + t + 4]);
            uint32_t a3 = __float_as_uint(Ps[(qrow + g + 8) * PS_STRIDE + kc + t + 4]);
#pragma unroll
            for (int dt = 0; dt < 16; dt++) {
                int dv = nw * 128 + dt * 8 + g;
                uint32_t b0 = __float_as_uint(Vs[(kc + t) * VS_STRIDE + dv]);
                uint32_t b1 = __float_as_uint(Vs[(kc + t + 4) * VS_STRIDE + dv]);
                mma_tf32(o[dt], a0, a1, a2, a3, b0, b1);
            }
        }
    }

    float inv0 = 1.f / l0;
    float inv1 = 1.f / l1;
    int row0 = b * S_LEN + qt * 128 + qrow + g;
    int row1 = row0 + 8;
#pragma unroll
    for (int dt = 0; dt < 16; dt++) {
        int col = h * V_HD_ + nw * 128 + dt * 8 + 2 * t;
        float2 v0 = make_float2(to_tf32(o[dt][0] * inv0), to_tf32(o[dt][1] * inv0));
        float2 v1 = make_float2(to_tf32(o[dt][2] * inv1), to_tf32(o[dt][3] * inv1));
        *(float2*)(attn + (size_t)row0 * (NH * V_HD_) + col) = v0;
        *(float2*)(attn + (size_t)row1 * (NH * V_HD_) + col) = v1;
    }
}

// ---------------- host launcher ----------------
extern "C" void kernel_launch(void* const* d_in, const int* in_sizes, int n_in,
                              void* d_out, int out_size)
{
    const float* x         = (const float*)d_in[0];
    const int*   pos       = (const int*)  d_in[1];
    const float* w_dq_w    = (const float*)d_in[2];
    const float* w_dq_b    = (const float*)d_in[3];
    const float* q_norm_w  = (const float*)d_in[4];
    const float* w_uq_qr_w = (const float*)d_in[5];
    const float* w_uq_qr_b = (const float*)d_in[6];
    const float* w_dkv_kr_w= (const float*)d_in[7];
    const float* w_dkv_kr_b= (const float*)d_in[8];
    const float* kv_norm_w = (const float*)d_in[9];
    const float* w_uk_uv_w = (const float*)d_in[10];
    const float* w_uk_uv_b = (const float*)d_in[11];
    const float* w_o_w     = (const float*)d_in[12];
    const float* w_o_b     = (const float*)d_in[13];
    float* out = (float*)d_out;

    float *cqkv, *q, *kv, *qsb, *ksb, *vsb, *attn;
    float *x32, *w13, *b13, *w2, *w4, *w5;
    cudaGetSymbolAddress((void**)&cqkv, g_cqkv);
    cudaGetSymbolAddress((void**)&q,    g_q);
    cudaGetSymbolAddress((void**)&kv,   g_kv);
    cudaGetSymbolAddress((void**)&qsb,  g_qs);
    cudaGetSymbolAddress((void**)&ksb,  g_ks);
    cudaGetSymbolAddress((void**)&vsb,  g_vs);
    cudaGetSymbolAddress((void**)&attn, g_attn);
    cudaGetSymbolAddress((void**)&x32,  g_x32);
    cudaGetSymbolAddress((void**)&w13,  g_w13);
    cudaGetSymbolAddress((void**)&b13,  g_b13);
    cudaGetSymbolAddress((void**)&w2,   g_w2);
    cudaGetSymbolAddress((void**)&w4,   g_w4);
    cudaGetSymbolAddress((void**)&w5,   g_w5);

    cudaFuncSetAttribute(flash_mma_kernel, cudaFuncAttributeMaxDynamicSharedMemorySize,
                         FLASH_SMEM_BYTES);
    cudaFuncSetAttribute(gemm_tf32_kernel, cudaFuncAttributeMaxDynamicSharedMemorySize,
                         GEMM_SMEM_BYTES);

    // fused tf32 rounding + weight packing
    round_all_kernel<<<(RA_TOTAL + 255) / 256, 256>>>(
        x, x32, w_uq_qr_w, w2, w_uk_uv_w, w4, w_o_w, w5,
        w_dq_w, w_dkv_kr_w, w13, w_dq_b, w_dkv_kr_b, b13);

    dim3 blk(256);

    // fused: cqkv = x @ [w_dq | w_dkv_kr | 0] + [b_dq | b_dkv_kr | 0]
    gemm_tf32_kernel<<<dim3(CQKV_N / GBN, NROWS / GBM), blk, GEMM_SMEM_BYTES>>>(
        x32, DIM_, w13, b13, cqkv, NROWS, CQKV_N, DIM_);
    rmsnorm_kernel<<<NROWS / 8, 256>>>(cqkv, q_norm_w, NROWS, CQKV_N);         // cq cols 0-127
    rmsnorm_kernel<<<NROWS / 8, 256>>>(cqkv + 128, kv_norm_w, NROWS, CQKV_N);  // ckv cols 128-255

    gemm_tf32_kernel<<<dim3(1024 / GBN, NROWS / GBM), blk, GEMM_SMEM_BYTES>>>(
        cqkv, CQKV_N, w2, w_uq_qr_b, q, NROWS, 1024, 128);

    gemm_tf32_kernel<<<dim3(2560 / GBN, NROWS / GBM), blk, GEMM_SMEM_BYTES>>>(
        cqkv + 128, CQKV_N, w4, w_uk_uv_b, kv, NROWS, 2560, 128);

    pack_q_kernel<<<(BATCH * NH * S_LEN * QDIM) / 256, 256>>>(q, pos, qsb);
    pack_k_kernel<<<(BATCH * NH * S_LEN * KDIM) / 256, 256>>>(kv, cqkv, pos, ksb);
    pack_v_kernel<<<(BATCH * NH * S_LEN * V_HD_) / 256, 256>>>(kv, vsb);

    flash_mma_kernel<<<dim3(S_LEN / 128, NH, BATCH), 512, FLASH_SMEM_BYTES>>>(qsb, ksb, vsb, attn);

    gemm_tf32_kernel<<<dim3(1024 / GBN, NROWS / GBM), blk, GEMM_SMEM_BYTES>>>(
        attn, NH * V_HD_, w5, w_o_b, out, NROWS, 1024, 2048);
}

// round 8
// speedup vs baseline: 4.4236x; 1.0471x over previous
#include <cuda_runtime.h>
#include <math.h>
#include <stdint.h>

// ---------------- problem constants ----------------
#define BATCH   2
#define S_LEN   2048
#define NROWS   (BATCH * S_LEN)     // 4096
#define DIM_    1024
#define NH      8
#define Q_C_    128
#define Q_NOPE_ 96
#define Q_ROPE_ 32
#define KV_C_   128
#define K_NOPE_ 64
#define K_ROPE_ 64
#define V_HD_   256
#define QDIM    128
#define KDIM    128
#define SM_SCALE 0.08838834764831845f   // 1/sqrt(128)
#define CQKV_N  384                      // 128 (cq) + 192 (ckv_kr) + 64 pad

// ---------------- scratch (static device arrays; no allocations) ----------------
__device__ float g_cqkv [(size_t)NROWS * CQKV_N];
__device__ float g_qs   [(size_t)BATCH * NH * S_LEN * QDIM];
__device__ float g_ks   [(size_t)BATCH * NH * S_LEN * KDIM];
__device__ float g_vs   [(size_t)BATCH * NH * S_LEN * V_HD_];
__device__ float g_attn [(size_t)NROWS * (NH * V_HD_)];
// tf32-rounded operands
__device__ float g_x32  [(size_t)NROWS * DIM_];
__device__ float g_w13  [(size_t)DIM_ * CQKV_N];
__device__ float g_b13  [CQKV_N];
__device__ float g_w2   [(size_t)Q_C_ * 1024];
__device__ float g_w4   [(size_t)KV_C_ * 2560];
__device__ float g_w5   [(size_t)2048 * DIM_];

// ---------------- helpers ----------------
__device__ __forceinline__ float to_tf32(float x) {
    uint32_t u;
    asm("cvt.rna.tf32.f32 %0, %1;" : "=r"(u) : "f"(x));
    return __uint_as_float(u);
}

__device__ __forceinline__ void mma_tf32(float* c, uint32_t a0, uint32_t a1,
                                         uint32_t a2, uint32_t a3,
                                         uint32_t b0, uint32_t b1) {
    asm volatile(
        "mma.sync.aligned.m16n8k8.row.col.f32.tf32.tf32.f32 "
        "{%0,%1,%2,%3}, {%4,%5,%6,%7}, {%8,%9}, {%0,%1,%2,%3};"
        : "+f"(c[0]), "+f"(c[1]), "+f"(c[2]), "+f"(c[3])
        : "r"(a0), "r"(a1), "r"(a2), "r"(a3), "r"(b0), "r"(b1));
}

__device__ __forceinline__ void cp_async16(void* smem_ptr, const void* gptr) {
    uint32_t s = (uint32_t)__cvta_generic_to_shared(smem_ptr);
    asm volatile("cp.async.cg.shared.global [%0], [%1], 16;" :: "r"(s), "l"(gptr));
}
#define CP_COMMIT() asm volatile("cp.async.commit_group;")
#define CP_WAIT0()  asm volatile("cp.async.wait_group 0;")
#define CP_WAIT1()  asm volatile("cp.async.wait_group 1;")

// ---------------- fused tf32 rounding / weight packing pass ----------------
#define RA_X   1048576
#define RA_W2  (RA_X  + 32768)
#define RA_W4  (RA_W2 + 81920)
#define RA_W5  (RA_W4 + 524288)
#define RA_W13 (RA_W5 + 98304)
#define RA_B13 (RA_W13 + 96)
#define RA_TOTAL RA_B13

__global__ __launch_bounds__(256)
void round_all_kernel(const float* __restrict__ x,    float* __restrict__ ox,
                      const float* __restrict__ w2i,  float* __restrict__ w2o,
                      const float* __restrict__ w4i,  float* __restrict__ w4o,
                      const float* __restrict__ w5i,  float* __restrict__ w5o,
                      const float* __restrict__ w1i,  const float* __restrict__ w3i,
                      float* __restrict__ w13o,
                      const float* __restrict__ b1i,  const float* __restrict__ b3i,
                      float* __restrict__ b13o)
{
    int i = blockIdx.x * 256 + threadIdx.x;
    if (i >= RA_TOTAL) return;
    float4 v;
    float4* dst;
    if (i < RA_X)       { v = ((const float4*)x)[i];             dst = (float4*)ox  + i; }
    else if (i < RA_W2) { int o = i - RA_X;  v = ((const float4*)w2i)[o]; dst = (float4*)w2o + o; }
    else if (i < RA_W4) { int o = i - RA_W2; v = ((const float4*)w4i)[o]; dst = (float4*)w4o + o; }
    else if (i < RA_W5) { int o = i - RA_W4; v = ((const float4*)w5i)[o]; dst = (float4*)w5o + o; }
    else if (i < RA_W13) {
        int o = i - RA_W5;
        int k = o / 96, c4 = (o % 96) * 4;
        if (c4 < 128)      v = *(const float4*)(w1i + (size_t)k * 128 + c4);
        else if (c4 < 320) v = *(const float4*)(w3i + (size_t)k * 192 + (c4 - 128));
        else               v = make_float4(0.f, 0.f, 0.f, 0.f);
        dst = (float4*)w13o + o;
    } else {
        int o = i - RA_W13;
        int c4 = o * 4;
        if (c4 < 128)      v = *(const float4*)(b1i + c4);
        else if (c4 < 320) v = *(const float4*)(b3i + (c4 - 128));
        else               v = make_float4(0.f, 0.f, 0.f, 0.f);
        *(float4*)(b13o + c4) = v;
        return;
    }
    v.x = to_tf32(v.x); v.y = to_tf32(v.y);
    v.z = to_tf32(v.z); v.w = to_tf32(v.w);
    *dst = v;
}

// ================= TF32 GEMM core (CTA 128x128, BK=32, 256 thr) =================
#define GBM 128
#define GBN 128
#define GBK 32
#define AS_STRIDE 36
#define BS_STRIDE 136
#define ABUF (GBM * AS_STRIDE)
#define BBUF (GBK * BS_STRIDE)
#define GEMM_SMEM_FLOATS (2 * (ABUF + BBUF))
#define GEMM_SMEM_BYTES  (GEMM_SMEM_FLOATS * 4)

// mainloop producing acc[2][8][4]; shared by all GEMM variants
#define GEMM_MAINLOOP(A, lda, B, N, K, m0, n0)                                        \
    float acc[2][8][4];                                                               \
    _Pragma("unroll") for (int mi = 0; mi < 2; mi++)                                  \
    _Pragma("unroll") for (int ni = 0; ni < 8; ni++)                                  \
    _Pragma("unroll") for (int j = 0; j < 4; j++) acc[mi][ni][j] = 0.f;               \
    int nk = (K) / GBK;                                                               \
    auto load_tile = [&](int kt, int bufi) {                                          \
        float* As_ = sm + bufi * (ABUF + BBUF);                                       \
        float* Bs_ = As_ + ABUF;                                                      \
        int k0 = kt * GBK;                                                            \
        _Pragma("unroll") for (int p = 0; p < 4; p++) {                               \
            int idx = tid + p * 256;                                                  \
            int r = idx >> 3, c = (idx & 7) * 4;                                      \
            cp_async16(&As_[r * AS_STRIDE + c], (A) + (size_t)((m0) + r) * (lda) + k0 + c); \
        }                                                                             \
        _Pragma("unroll") for (int p = 0; p < 4; p++) {                               \
            int idx = tid + p * 256;                                                  \
            int r = idx >> 5, c = (idx & 31) * 4;                                     \
            cp_async16(&Bs_[r * BS_STRIDE + c], (B) + (size_t)(k0 + r) * (N) + (n0) + c); \
        }                                                                             \
        CP_COMMIT();                                                                  \
    };                                                                                \
    load_tile(0, 0);                                                                  \
    for (int kt = 0; kt < nk; kt++) {                                                 \
        int bufi = kt & 1;                                                            \
        if (kt + 1 < nk) { load_tile(kt + 1, bufi ^ 1); CP_WAIT1(); }                 \
        else            { CP_WAIT0(); }                                               \
        __syncthreads();                                                              \
        const float* As_ = sm + bufi * (ABUF + BBUF);                                 \
        const float* Bs_ = As_ + ABUF;                                                \
        _Pragma("unroll") for (int k8 = 0; k8 < 4; k8++) {                            \
            int kc = k8 * 8;                                                          \
            uint32_t a[2][4];                                                         \
            _Pragma("unroll") for (int mi = 0; mi < 2; mi++) {                        \
                int row = wm * 32 + mi * 16;                                          \
                a[mi][0] = __float_as_uint(As_[(row + g) * AS_STRIDE + kc + t]);      \
                a[mi][1] = __float_as_uint(As_[(row + g + 8) * AS_STRIDE + kc + t]);  \
                a[mi][2] = __float_as_uint(As_[(row + g) * AS_STRIDE + kc + t + 4]);  \
                a[mi][3] = __float_as_uint(As_[(row + g + 8) * AS_STRIDE + kc + t + 4]); \
            }                                                                         \
            _Pragma("unroll") for (int ni = 0; ni < 8; ni++) {                        \
                int col = wn * 64 + ni * 8 + g;                                       \
                uint32_t b0 = __float_as_uint(Bs_[(kc + t) * BS_STRIDE + col]);       \
                uint32_t b1 = __float_as_uint(Bs_[(kc + t + 4) * BS_STRIDE + col]);   \
                mma_tf32(acc[0][ni], a[0][0], a[0][1], a[0][2], a[0][3], b0, b1);     \
                mma_tf32(acc[1][ni], a[1][0], a[1][1], a[1][2], a[1][3], b0, b1);     \
            }                                                                         \
        }                                                                             \
        __syncthreads();                                                              \
    }

#define GEMM_PREAMBLE                  \
    extern __shared__ float sm[];      \
    int tid  = threadIdx.x;            \
    int wid  = tid >> 5;               \
    int lane = tid & 31;               \
    int wm = wid >> 1;                 \
    int wn = wid & 1;                  \
    int g  = lane >> 2;                \
    int t  = lane & 3;

// ---------------- plain GEMM + bias, fp32 out ----------------
__global__ __launch_bounds__(256, 2)
void gemm_tf32_kernel(const float* __restrict__ A, int lda,
                      const float* __restrict__ B,
                      const float* __restrict__ bias,
                      float* __restrict__ C,
                      int M, int N, int K)
{
    GEMM_PREAMBLE
    int m0 = blockIdx.y * GBM;
    int n0 = blockIdx.x * GBN;
    GEMM_MAINLOOP(A, lda, B, N, K, m0, n0)

#pragma unroll
    for (int ni = 0; ni < 8; ni++) {
        int col = n0 + wn * 64 + ni * 8 + 2 * t;
        float2 bv = *(const float2*)(bias + col);
#pragma unroll
        for (int mi = 0; mi < 2; mi++) {
            int r0 = m0 + wm * 32 + mi * 16 + g;
            float2 v0 = make_float2(acc[mi][ni][0] + bv.x, acc[mi][ni][1] + bv.y);
            float2 v1 = make_float2(acc[mi][ni][2] + bv.x, acc[mi][ni][3] + bv.y);
            *(float2*)(C + (size_t)r0 * N + col) = v0;
            *(float2*)(C + (size_t)(r0 + 8) * N + col) = v1;
        }
    }
}

// ---------------- q-projection GEMM with fused RoPE + scale + qs-layout epilogue ----------------
// C layout target: qs[((b*8+h)*2048+s)*128 + d], nope cols 0-767, rope cols 768-1023.
__global__ __launch_bounds__(256, 2)
void gemm_q_kernel(const float* __restrict__ A, int lda,
                   const float* __restrict__ B,
                   const float* __restrict__ bias,
                   const int* __restrict__ pos,
                   float* __restrict__ qs,
                   int M, int N, int K)
{
    GEMM_PREAMBLE
    int m0 = blockIdx.y * GBM;
    int n0 = blockIdx.x * GBN;
    GEMM_MAINLOOP(A, lda, B, N, K, m0, n0)

#pragma unroll
    for (int ni = 0; ni < 8; ni++) {
        int col = n0 + wn * 64 + ni * 8 + 2 * t;
        float2 bv = *(const float2*)(bias + col);
#pragma unroll
        for (int mi = 0; mi < 2; mi++) {
#pragma unroll
            for (int half = 0; half < 2; half++) {
                int row = m0 + wm * 32 + mi * 16 + g + half * 8;
                float c0 = acc[mi][ni][half * 2 + 0] + bv.x;
                float c1 = acc[mi][ni][half * 2 + 1] + bv.y;
                int b = row >> 11, s = row & 2047;
                int h, d;
                float o0, o1;
                if (col < 768) {
                    h = col / 96; d = col % 96;
                    o0 = c0; o1 = c1;
                } else {
                    int cc = col - 768;
                    h = cc >> 5;
                    int j = cc & 31;
                    int i = j >> 1;
                    float ang = (float)pos[row] * powf(10000.f, -(float)(2 * i) / 32.f);
                    float sn, cs;
                    sincosf(ang, &sn, &cs);
                    o0 = c0 * cs - c1 * sn;
                    o1 = c0 * sn + c1 * cs;
                    d = 96 + j;
                }
                float* dst = qs + (((size_t)(b * 8 + h) * 2048 + s) * 128 + d);
                dst[0] = to_tf32(o0 * SM_SCALE);
                dst[1] = to_tf32(o1 * SM_SCALE);
            }
        }
    }
}

// ---------------- kv-projection GEMM with fused ks/vs-layout epilogue ----------------
// cols 0-511: k_nope -> ks[..., d<64]; cols 512-2559: v -> vs[..., d<256]
__global__ __launch_bounds__(256, 2)
void gemm_kv_kernel(const float* __restrict__ A, int lda,
                    const float* __restrict__ B,
                    const float* __restrict__ bias,
                    float* __restrict__ ks, float* __restrict__ vs,
                    int M, int N, int K)
{
    GEMM_PREAMBLE
    int m0 = blockIdx.y * GBM;
    int n0 = blockIdx.x * GBN;
    GEMM_MAINLOOP(A, lda, B, N, K, m0, n0)

#pragma unroll
    for (int ni = 0; ni < 8; ni++) {
        int col = n0 + wn * 64 + ni * 8 + 2 * t;
        float2 bv = *(const float2*)(bias + col);
#pragma unroll
        for (int mi = 0; mi < 2; mi++) {
#pragma unroll
            for (int half = 0; half < 2; half++) {
                int row = m0 + wm * 32 + mi * 16 + g + half * 8;
                float c0 = acc[mi][ni][half * 2 + 0] + bv.x;
                float c1 = acc[mi][ni][half * 2 + 1] + bv.y;
                int b = row >> 11, s = row & 2047;
                float* dst;
                if (col < 512) {
                    int h = col >> 6, d = col & 63;
                    dst = ks + (((size_t)(b * 8 + h) * 2048 + s) * 128 + d);
                } else {
                    int cc = col - 512;
                    int h = cc >> 8, d = cc & 255;
                    dst = vs + (((size_t)(b * 8 + h) * 2048 + s) * 256 + d);
                }
                dst[0] = to_tf32(c0);
                dst[1] = to_tf32(c1);
            }
        }
    }
}

// ---------------- merged RMSNorm: cq (cols 0-127) + ckv (cols 128-255) ----------------
__global__ void rmsnorm2_kernel(float* __restrict__ cqkv,
                                const float* __restrict__ wq,
                                const float* __restrict__ wkv)
{
    int row = blockIdx.x * 8 + (threadIdx.x >> 5);
    int lane = threadIdx.x & 31;
    float* p = cqkv + (size_t)row * CQKV_N;
#pragma unroll
    for (int half = 0; half < 2; half++) {
        float* q = p + half * 128;
        const float* w = half ? wkv : wq;
        float4 v = *(float4*)(q + lane * 4);
        float ss = v.x * v.x + v.y * v.y + v.z * v.z + v.w * v.w;
#pragma unroll
        for (int o = 16; o; o >>= 1) ss += __shfl_xor_sync(0xffffffffu, ss, o);
        float sc = rsqrtf(ss * (1.f / 128.f) + 1e-8f);
        float4 wv = *(const float4*)(w + lane * 4);
        v.x = to_tf32(v.x * wv.x * sc);
        v.y = to_tf32(v.y * wv.y * sc);
        v.z = to_tf32(v.z * wv.z * sc);
        v.w = to_tf32(v.w * wv.w * sc);
        *(float4*)(q + lane * 4) = v;
    }
}

// ---------------- k_rope pack: rope(cqkv cols 256-319) broadcast to 8 heads ----------------
__global__ void pack_k_rope_kernel(const float* __restrict__ cqkv,
                                   const int* __restrict__ pos,
                                   float* __restrict__ ks)
{
    int idx = blockIdx.x * blockDim.x + threadIdx.x;   // [b, s, i] i<32 pairs
    if (idx >= BATCH * S_LEN * 32) return;
    int i = idx & 31;
    int s = (idx >> 5) & 2047;
    int b = idx >> 16;
    int r = b * 2048 + s;
    const float* base = cqkv + (size_t)r * CQKV_N + 256;
    float xe = base[2 * i];
    float xo = base[2 * i + 1];
    float ang = (float)pos[r] * powf(10000.f, -(float)(2 * i) / 64.f);
    float sn, cs;
    sincosf(ang, &sn, &cs);
    float v0 = to_tf32(xe * cs - xo * sn);
    float v1 = to_tf32(xe * sn + xo * cs);
#pragma unroll
    for (int h = 0; h < 8; h++) {
        float* dst = ks + (((size_t)(b * 8 + h) * 2048 + s) * 128 + 64 + 2 * i);
        dst[0] = v0;
        dst[1] = v1;
    }
}

// ---------------- TF32 tensor-core flash attention (cp.async pipelined) ----------------
#define QS_STRIDE 132
#define KS_STRIDE 132
#define VS_STRIDE 260
#define PS_STRIDE 68
#define QS_OFF  0
#define KS_OFF  (QS_OFF + 128 * QS_STRIDE)
#define VS_OFF  (KS_OFF + 64 * KS_STRIDE)
#define PS_OFF  (VS_OFF + 64 * VS_STRIDE)
#define STM_OFF (PS_OFF + 128 * PS_STRIDE)
#define STS_OFF (STM_OFF + 256)
#define FLASH_SMEM_FLOATS (STS_OFF + 256)
#define FLASH_SMEM_BYTES  (FLASH_SMEM_FLOATS * 4)
#define NKT (S_LEN / 64)

__global__ __launch_bounds__(512, 1)
void flash_mma_kernel(const float* __restrict__ qs, const float* __restrict__ ks,
                      const float* __restrict__ vs, float* __restrict__ attn)
{
    extern __shared__ float sm[];
    float* Qs  = sm + QS_OFF;
    float* Ks  = sm + KS_OFF;
    float* Vs  = sm + VS_OFF;
    float* Ps  = sm + PS_OFF;
    float* StM = sm + STM_OFF;
    float* StS = sm + STS_OFF;

    int b = blockIdx.z, h = blockIdx.y, qt = blockIdx.x;
    int tid  = threadIdx.x;
    int wid  = tid >> 5;
    int lane = tid & 31;
    int mw = wid >> 1;
    int nw = wid & 1;
    int g  = lane >> 2;
    int t  = lane & 3;

    size_t bh = (size_t)(b * NH + h) * S_LEN;

    auto load_k_tile = [&](int kt) {
        const float* Kg = ks + (bh + (size_t)kt * 64) * 128;
#pragma unroll
        for (int p = 0; p < 4; p++) {
            int idx = tid + p * 512;
            int r = idx >> 5, c = (idx & 31) * 4;
            cp_async16(&Ks[r * KS_STRIDE + c], Kg + r * 128 + c);
        }
        CP_COMMIT();
    };
    auto load_v_tile = [&](int kt) {
        const float* Vg = vs + (bh + (size_t)kt * 64) * 256;
#pragma unroll
        for (int p = 0; p < 8; p++) {
            int idx = tid + p * 512;
            int r = idx >> 6, c = (idx & 63) * 4;
            cp_async16(&Vs[r * VS_STRIDE + c], Vg + r * 256 + c);
        }
        CP_COMMIT();
    };

    load_k_tile(0);
    {
        const float4* Qg = (const float4*)(qs + (bh + (size_t)qt * 128) * 128);
#pragma unroll
        for (int p = 0; p < 8; p++) {
            int r = wid + p * 16;
            *(float4*)&Qs[r * QS_STRIDE + lane * 4] = Qg[r * 32 + lane];
        }
    }

    int qrow = mw * 16;
    float m0 = -1e30f, m1 = -1e30f, l0 = 0.f, l1 = 0.f;
    float o[16][4];
#pragma unroll
    for (int dt = 0; dt < 16; dt++)
#pragma unroll
        for (int j = 0; j < 4; j++) o[dt][j] = 0.f;

    for (int kt = 0; kt < NKT; kt++) {
        CP_WAIT0();
        __syncthreads();

        load_v_tile(kt);

        float c[4][4];
#pragma unroll
        for (int nt = 0; nt < 4; nt++)
#pragma unroll
            for (int j = 0; j < 4; j++) c[nt][j] = 0.f;

#pragma unroll
        for (int k8 = 0; k8 < 16; k8++) {
            int kc = k8 * 8;
            uint32_t a0 = __float_as_uint(Qs[(qrow + g) * QS_STRIDE + kc + t]);
            uint32_t a1 = __float_as_uint(Qs[(qrow + g + 8) * QS_STRIDE + kc + t]);
            uint32_t a2 = __float_as_uint(Qs[(qrow + g) * QS_STRIDE + kc + t + 4]);
            uint32_t a3 = __float_as_uint(Qs[(qrow + g + 8) * QS_STRIDE + kc + t + 4]);
#pragma unroll
            for (int nt = 0; nt < 4; nt++) {
                int ncol = nw * 32 + nt * 8 + g;
                uint32_t b0 = __float_as_uint(Ks[ncol * KS_STRIDE + kc + t]);
                uint32_t b1 = __float_as_uint(Ks[ncol * KS_STRIDE + kc + t + 4]);
                mma_tf32(c[nt], a0, a1, a2, a3, b0, b1);
            }
        }

        float pm0 = -1e30f, pm1 = -1e30f;
#pragma unroll
        for (int nt = 0; nt < 4; nt++) {
            pm0 = fmaxf(pm0, fmaxf(c[nt][0], c[nt][1]));
            pm1 = fmaxf(pm1, fmaxf(c[nt][2], c[nt][3]));
        }
        pm0 = fmaxf(pm0, __shfl_xor_sync(0xffffffffu, pm0, 1));
        pm0 = fmaxf(pm0, __shfl_xor_sync(0xffffffffu, pm0, 2));
        pm1 = fmaxf(pm1, __shfl_xor_sync(0xffffffffu, pm1, 1));
        pm1 = fmaxf(pm1, __shfl_xor_sync(0xffffffffu, pm1, 2));

        float ex[4][4];
        float ps0 = 0.f, ps1 = 0.f;
#pragma unroll
        for (int nt = 0; nt < 4; nt++) {
            ex[nt][0] = __expf(c[nt][0] - pm0);
            ex[nt][1] = __expf(c[nt][1] - pm0);
            ex[nt][2] = __expf(c[nt][2] - pm1);
            ex[nt][3] = __expf(c[nt][3] - pm1);
            ps0 += ex[nt][0] + ex[nt][1];
            ps1 += ex[nt][2] + ex[nt][3];
        }
        ps0 += __shfl_xor_sync(0xffffffffu, ps0, 1);
        ps0 += __shfl_xor_sync(0xffffffffu, ps0, 2);
        ps1 += __shfl_xor_sync(0xffffffffu, ps1, 1);
        ps1 += __shfl_xor_sync(0xffffffffu, ps1, 2);

        if (t == 0) {
            StM[nw * 128 + qrow + g]     = pm0;
            StM[nw * 128 + qrow + g + 8] = pm1;
            StS[nw * 128 + qrow + g]     = ps0;
            StS[nw * 128 + qrow + g + 8] = ps1;
        }
        __syncthreads();

        if (kt + 1 < NKT) load_k_tile(kt + 1);

        int ow = 1 - nw;
        float pmO0 = StM[ow * 128 + qrow + g];
        float pmO1 = StM[ow * 128 + qrow + g + 8];
        float psO0 = StS[ow * 128 + qrow + g];
        float psO1 = StS[ow * 128 + qrow + g + 8];

        float mn0 = fmaxf(pm0, pmO0);
        float mn1 = fmaxf(pm1, pmO1);
        float rs0 = ps0 * __expf(pm0 - mn0) + psO0 * __expf(pmO0 - mn0);
        float rs1 = ps1 * __expf(pm1 - mn1) + psO1 * __expf(pmO1 - mn1);

        float mnew0 = fmaxf(m0, mn0);
        float mnew1 = fmaxf(m1, mn1);
        float corr0 = __expf(m0 - mnew0);
        float corr1 = __expf(m1 - mnew1);
        l0 = l0 * corr0 + rs0 * __expf(mn0 - mnew0);
        l1 = l1 * corr1 + rs1 * __expf(mn1 - mnew1);
        m0 = mnew0;
        m1 = mnew1;

#pragma unroll
        for (int dt = 0; dt < 16; dt++) {
            o[dt][0] *= corr0;
            o[dt][1] *= corr0;
            o[dt][2] *= corr1;
            o[dt][3] *= corr1;
        }

        float f0 = __expf(pm0 - mnew0);
        float f1 = __expf(pm1 - mnew1);
#pragma unroll
        for (int nt = 0; nt < 4; nt++) {
            int col = nw * 32 + nt * 8 + 2 * t;
            Ps[(qrow + g) * PS_STRIDE + col]         = to_tf32(ex[nt][0] * f0);
            Ps[(qrow + g) * PS_STRIDE + col + 1]     = to_tf32(ex[nt][1] * f0);
            Ps[(qrow + g + 8) * PS_STRIDE + col]     = to_tf32(ex[nt][2] * f1);
            Ps[(qrow + g + 8) * PS_STRIDE + col + 1] = to_tf32(ex[nt][3] * f1);
        }

        if (kt + 1 < NKT) { CP_WAIT1(); } else { CP_WAIT0(); }
        __syncthreads();

#pragma unroll
        for (int k8 = 0; k8 < 8; k8++) {
            int kc = k8 * 8;
            uint32_t a0 = __float_as_uint(Ps[(qrow + g) * PS_STRIDE + kc + t]);
            uint32_t a1 = __float_as_uint(Ps[(qrow + g + 8) * PS_STRIDE + kc + t]);
            uint32_t a2 = __float_as_uint(Ps[(qrow + g) * PS_STRIDE + kc + t + 4]);
            uint32_t a3 = __float_as_uint(Ps[(qrow + g + 8) * PS_STRIDE + kc + t + 4]);
#pragma unroll
            for (int dt = 0; dt < 16; dt++) {
                int dv = nw * 128 + dt * 8 + g;
                uint32_t b0 = __float_as_uint(Vs[(kc + t) * VS_STRIDE + dv]);
                uint32_t b1 = __float_as_uint(Vs[(kc + t + 4) * VS_STRIDE + dv]);
                mma_tf32(o[dt], a0, a1, a2, a3, b0, b1);
            }
        }
    }

    float inv0 = 1.f / l0;
    float inv1 = 1.f / l1;
    int row0 = b * S_LEN + qt * 128 + qrow + g;
    int row1 = row0 + 8;
#pragma unroll
    for (int dt = 0; dt < 16; dt++) {
        int col = h * V_HD_ + nw * 128 + dt * 8 + 2 * t;
        float2 v0 = make_float2(to_tf32(o[dt][0] * inv0), to_tf32(o[dt][1] * inv0));
        float2 v1 = make_float2(to_tf32(o[dt][2] * inv1), to_tf32(o[dt][3] * inv1));
        *(float2*)(attn + (size_t)row0 * (NH * V_HD_) + col) = v0;
        *(float2*)(attn + (size_t)row1 * (NH * V_HD_) + col) = v1;
    }
}

// ---------------- host launcher ----------------
extern "C" void kernel_launch(void* const* d_in, const int* in_sizes, int n_in,
                              void* d_out, int out_size)
{
    const float* x         = (const float*)d_in[0];
    const int*   pos       = (const int*)  d_in[1];
    const float* w_dq_w    = (const float*)d_in[2];
    const float* w_dq_b    = (const float*)d_in[3];
    const float* q_norm_w  = (const float*)d_in[4];
    const float* w_uq_qr_w = (const float*)d_in[5];
    const float* w_uq_qr_b = (const float*)d_in[6];
    const float* w_dkv_kr_w= (const float*)d_in[7];
    const float* w_dkv_kr_b= (const float*)d_in[8];
    const float* kv_norm_w = (const float*)d_in[9];
    const float* w_uk_uv_w = (const float*)d_in[10];
    const float* w_uk_uv_b = (const float*)d_in[11];
    const float* w_o_w     = (const float*)d_in[12];
    const float* w_o_b     = (const float*)d_in[13];
    float* out = (float*)d_out;

    float *cqkv, *qsb, *ksb, *vsb, *attn;
    float *x32, *w13, *b13, *w2, *w4, *w5;
    cudaGetSymbolAddress((void**)&cqkv, g_cqkv);
    cudaGetSymbolAddress((void**)&qsb,  g_qs);
    cudaGetSymbolAddress((void**)&ksb,  g_ks);
    cudaGetSymbolAddress((void**)&vsb,  g_vs);
    cudaGetSymbolAddress((void**)&attn, g_attn);
    cudaGetSymbolAddress((void**)&x32,  g_x32);
    cudaGetSymbolAddress((void**)&w13,  g_w13);
    cudaGetSymbolAddress((void**)&b13,  g_b13);
    cudaGetSymbolAddress((void**)&w2,   g_w2);
    cudaGetSymbolAddress((void**)&w4,   g_w4);
    cudaGetSymbolAddress((void**)&w5,   g_w5);

    cudaFuncSetAttribute(flash_mma_kernel, cudaFuncAttributeMaxDynamicSharedMemorySize,
                         FLASH_SMEM_BYTES);
    cudaFuncSetAttribute(gemm_tf32_kernel, cudaFuncAttributeMaxDynamicSharedMemorySize,
                         GEMM_SMEM_BYTES);
    cudaFuncSetAttribute(gemm_q_kernel, cudaFuncAttributeMaxDynamicSharedMemorySize,
                         GEMM_SMEM_BYTES);
    cudaFuncSetAttribute(gemm_kv_kernel, cudaFuncAttributeMaxDynamicSharedMemorySize,
                         GEMM_SMEM_BYTES);

    round_all_kernel<<<(RA_TOTAL + 255) / 256, 256>>>(
        x, x32, w_uq_qr_w, w2, w_uk_uv_w, w4, w_o_w, w5,
        w_dq_w, w_dkv_kr_w, w13, w_dq_b, w_dkv_kr_b, b13);

    dim3 blk(256);

    gemm_tf32_kernel<<<dim3(CQKV_N / GBN, NROWS / GBM), blk, GEMM_SMEM_BYTES>>>(
        x32, DIM_, w13, b13, cqkv, NROWS, CQKV_N, DIM_);

    rmsnorm2_kernel<<<NROWS / 8, 256>>>(cqkv, q_norm_w, kv_norm_w);

    // q projection, epilogue writes qs directly (RoPE + scale + tf32)
    gemm_q_kernel<<<dim3(1024 / GBN, NROWS / GBM), blk, GEMM_SMEM_BYTES>>>(
        cqkv, CQKV_N, w2, w_uq_qr_b, pos, qsb, NROWS, 1024, 128);

    // kv projection, epilogue writes ks (nope) + vs directly
    gemm_kv_kernel<<<dim3(2560 / GBN, NROWS / GBM), blk, GEMM_SMEM_BYTES>>>(
        cqkv + 128, CQKV_N, w4, w_uk_uv_b, ksb, vsb, NROWS, 2560, 128);

    // k_rope from cqkv, broadcast to heads
    pack_k_rope_kernel<<<(BATCH * S_LEN * 32) / 256, 256>>>(cqkv, pos, ksb);

    flash_mma_kernel<<<dim3(S_LEN / 128, NH, BATCH), 512, FLASH_SMEM_BYTES>>>(qsb, ksb, vsb, attn);

    gemm_tf32_kernel<<<dim3(1024 / GBN, NROWS / GBM), blk, GEMM_SMEM_BYTES>>>(
        attn, NH * V_HD_, w5, w_o_b, out, NROWS, 1024, 2048);
}